// round 11
// baseline (speedup 1.0000x reference)
#include <cuda_runtime.h>
#include <cuda_bf16.h>
#include <cstdint>

// ---------------- problem constants ----------------
#define BATCH  2
#define TSEQ   2048
#define BT     4096      // BATCH*TSEQ
#define HID    1536
#define NH     12
#define DK     16
#define DV     128
#define QKDIM  192       // NH*DK
#define QK2    384       // fused Q+K projection width
#define DREAL  273       // 1 + 16 + 256
#define DP     320       // padded feature dim
#define CHUNK  128
#define NCK    16        // TSEQ/CHUNK
#define BH     24        // BATCH*NH
#define NCH    384       // BH*NCK
#define EPSV   1e-12f

// ---------------- scratch (device globals, alloc-free) ----------------
__device__ float g_qk [(size_t)BT*QK2];
__device__ float g_k1 [(size_t)NCH*DP];
__device__ float g_den[(size_t)BH*TSEQ];

// bf16 split operands
__device__ __nv_bfloat16 g_xh [(size_t)BT*HID];
__device__ __nv_bfloat16 g_xl [(size_t)BT*HID];
__device__ __nv_bfloat16 g_yh [(size_t)BT*HID];
__device__ __nv_bfloat16 g_yl [(size_t)BT*HID];
__device__ __nv_bfloat16 g_vh [(size_t)BT*HID];
__device__ __nv_bfloat16 g_vl [(size_t)BT*HID];
__device__ __nv_bfloat16 g_qfh[(size_t)BH*TSEQ*DP];
__device__ __nv_bfloat16 g_qfl[(size_t)BH*TSEQ*DP];
__device__ __nv_bfloat16 g_kfh[(size_t)BH*TSEQ*DP];
__device__ __nv_bfloat16 g_kfl[(size_t)BH*TSEQ*DP];
__device__ __nv_bfloat16 g_kvh[(size_t)NCH*DP*DV];
__device__ __nv_bfloat16 g_kvl[(size_t)NCH*DP*DV];
__device__ __nv_bfloat16 g_wqkh[(size_t)QK2*HID];
__device__ __nv_bfloat16 g_wqkl[(size_t)QK2*HID];
__device__ __nv_bfloat16 g_wvh[(size_t)HID*HID];
__device__ __nv_bfloat16 g_wvl[(size_t)HID*HID];
__device__ __nv_bfloat16 g_woh[(size_t)HID*HID];
__device__ __nv_bfloat16 g_wol[(size_t)HID*HID];

// ---------------- helpers ----------------
__device__ __forceinline__ uint32_t smem_u32(const void* p) {
    uint32_t a;
    asm("{ .reg .u64 t; cvta.to.shared.u64 t, %1; cvt.u32.u64 %0, t; }" : "=r"(a) : "l"(p));
    return a;
}
__device__ __forceinline__ void cp_async16(uint32_t dst, const void* src) {
    asm volatile("cp.async.cg.shared.global [%0], [%1], 16;" :: "r"(dst), "l"(src));
}
#define CP_COMMIT() asm volatile("cp.async.commit_group;" ::: "memory")
#define CP_WAIT(N)  asm volatile("cp.async.wait_group %0;" :: "n"(N) : "memory")

__device__ __forceinline__ void ldmat4(uint32_t* r, uint32_t addr) {
    asm volatile("ldmatrix.sync.aligned.m8n8.x4.shared.b16 {%0,%1,%2,%3}, [%4];"
                 : "=r"(r[0]), "=r"(r[1]), "=r"(r[2]), "=r"(r[3]) : "r"(addr));
}
__device__ __forceinline__ void ldmat4t(uint32_t* r, uint32_t addr) {
    asm volatile("ldmatrix.sync.aligned.m8n8.x4.trans.shared.b16 {%0,%1,%2,%3}, [%4];"
                 : "=r"(r[0]), "=r"(r[1]), "=r"(r[2]), "=r"(r[3]) : "r"(addr));
}
__device__ __forceinline__ void mma_bf16(float* d,
                                         uint32_t a0, uint32_t a1, uint32_t a2, uint32_t a3,
                                         uint32_t b0, uint32_t b1) {
    asm volatile("mma.sync.aligned.m16n8k16.row.col.f32.bf16.bf16.f32 "
                 "{%0,%1,%2,%3}, {%4,%5,%6,%7}, {%8,%9}, {%0,%1,%2,%3};"
                 : "+f"(d[0]), "+f"(d[1]), "+f"(d[2]), "+f"(d[3])
                 : "r"(a0), "r"(a1), "r"(a2), "r"(a3), "r"(b0), "r"(b1));
}
// split-3 product: Ah*Bh + Ah*Bl + Al*Bh
__device__ __forceinline__ void mma3(float* d, const uint32_t* ah, const uint32_t* al,
                                     uint32_t bh0, uint32_t bh1, uint32_t bl0, uint32_t bl1) {
    mma_bf16(d, ah[0], ah[1], ah[2], ah[3], bh0, bh1);
    mma_bf16(d, ah[0], ah[1], ah[2], ah[3], bl0, bl1);
    mma_bf16(d, al[0], al[1], al[2], al[3], bh0, bh1);
}

// fragment address helpers (lane-dependent); pitchB = row pitch in bytes
__device__ __forceinline__ uint32_t aaddr_nt(uint32_t base, int pitchB, int m_off, int k_off, int lane) {
    int row = m_off + (lane & 7) + ((lane >> 3) & 1) * 8;
    int col = k_off + ((lane >> 4) & 1) * 8;
    return base + row * pitchB + col * 2;
}
__device__ __forceinline__ uint32_t aaddr_t(uint32_t base, int pitchB, int m_off, int k_off, int lane) {
    int row = k_off + (lane & 7) + ((lane >> 4) & 1) * 8;
    int col = m_off + ((lane >> 3) & 1) * 8;
    return base + row * pitchB + col * 2;
}
__device__ __forceinline__ uint32_t baddr_nt(uint32_t base, int pitchB, int n_off, int k_off, int lane) {
    int row = n_off + (lane & 7) + ((lane >> 4) & 1) * 8;
    int col = k_off + ((lane >> 3) & 1) * 8;
    return base + row * pitchB + col * 2;
}
__device__ __forceinline__ uint32_t baddr_t(uint32_t base, int pitchB, int n_off, int k_off, int lane) {
    int row = k_off + (lane & 7) + ((lane >> 3) & 1) * 8;
    int col = n_off + ((lane >> 4) & 1) * 8;
    return base + row * pitchB + col * 2;
}

__device__ __forceinline__ void split2(float v, __nv_bfloat16& h, __nv_bfloat16& l) {
    h = __float2bfloat16(v);
    l = __float2bfloat16(v - __bfloat162float(h));
}

// ---------------- split conversion fp32 -> (hi, lo) bf16 ----------------
__global__ void cvt_split(const float* __restrict__ x, __nv_bfloat16* __restrict__ hi,
                          __nv_bfloat16* __restrict__ lo, size_t n) {
    size_t i = ((size_t)blockIdx.x * 256 + threadIdx.x) * 4;
    if (i >= n) return;
    float4 v = *(const float4*)(x + i);
    float a[4] = {v.x, v.y, v.z, v.w};
    __nv_bfloat16 h[4], l[4];
#pragma unroll
    for (int j = 0; j < 4; j++) split2(a[j], h[j], l[j]);
    ((__nv_bfloat162*)(hi + i))[0] = __nv_bfloat162(h[0], h[1]);
    ((__nv_bfloat162*)(hi + i))[1] = __nv_bfloat162(h[2], h[3]);
    ((__nv_bfloat162*)(lo + i))[0] = __nv_bfloat162(l[0], l[1]);
    ((__nv_bfloat162*)(lo + i))[1] = __nv_bfloat162(l[2], l[3]);
}

// ---------------- HMMA split-bf16 GEMM: C[M,N] = A[M,K] @ B[N,K]^T ----------------
#define GPITCH 40
#define MAT_BYTES (128 * GPITCH * 2)
#define STAGE_BYTES (4 * MAT_BYTES)
#define NSTAGE 4
#define SMEM_MMA (NSTAGE * STAGE_BYTES)     // 163840

template <bool SPLIT>
__global__ void __launch_bounds__(512) gemm_mma(
    const __nv_bfloat16* __restrict__ Ahg, const __nv_bfloat16* __restrict__ Alg,
    const __nv_bfloat16* __restrict__ Bhg, const __nv_bfloat16* __restrict__ Blg,
    float* __restrict__ C, __nv_bfloat16* __restrict__ Ch, __nv_bfloat16* __restrict__ Cl,
    int M, int N, int K) {
    extern __shared__ char smem[];
    const uint32_t sb = smem_u32(smem);
    const int tid = threadIdx.x, wid = tid >> 5, lane = tid & 31;
    const int wm = wid >> 2, wn = wid & 3;           // 4x4 warps, 32x32 tiles
    const int m0 = blockIdx.y * 128, n0 = blockIdx.x * 128;
    const int nch = K / 32;

    float acc[2][4][4] = {};

    auto load_chunk = [&](int c, int s) {
        const uint32_t base = sb + (uint32_t)s * STAGE_BYTES;
        const int kk = c * 32;
#pragma unroll
        for (int it = 0; it < 4; it++) {
            int idx = tid + it * 512;
            int mat = idx >> 9;
            int r   = (idx >> 2) & 127;
            int seg = idx & 3;
            uint32_t dst = base + (uint32_t)mat * MAT_BYTES + (uint32_t)(r * (GPITCH * 2) + seg * 16);
            const __nv_bfloat16* src;
            if (mat < 2) {
                const __nv_bfloat16* A = (mat == 0) ? Ahg : Alg;
                src = A + (size_t)(m0 + r) * K + kk + seg * 8;
            } else {
                const __nv_bfloat16* B = (mat == 2) ? Bhg : Blg;
                int row = n0 + r; if (row >= N) row = N - 1;
                src = B + (size_t)row * K + kk + seg * 8;
            }
            cp_async16(dst, src);
        }
        CP_COMMIT();
    };

    {
        int pf = (nch < 3) ? nch : 3;
        for (int s = 0; s < pf; s++) load_chunk(s, s);
    }

    for (int c = 0; c < nch; c++) {
        int out = nch - c; if (out > 3) out = 3;
        if (out == 3)      CP_WAIT(2);
        else if (out == 2) CP_WAIT(1);
        else               CP_WAIT(0);
        __syncthreads();
        if (c + 3 < nch) load_chunk(c + 3, (c + 3) & (NSTAGE - 1));

        const uint32_t base = sb + (uint32_t)(c & (NSTAGE - 1)) * STAGE_BYTES;
        const uint32_t bAh = base, bAl = base + MAT_BYTES;
        const uint32_t bBh = base + 2 * MAT_BYTES, bBl = base + 3 * MAT_BYTES;
#pragma unroll
        for (int s = 0; s < 32; s += 16) {
            uint32_t ah[2][4], al[2][4];
#pragma unroll
            for (int mt = 0; mt < 2; mt++) {
                uint32_t o = aaddr_nt(0, GPITCH * 2, wm * 32 + mt * 16, s, lane);
                ldmat4(ah[mt], bAh + o);
                ldmat4(al[mt], bAl + o);
            }
            uint32_t bh[2][4], bl[2][4];
#pragma unroll
            for (int p = 0; p < 2; p++) {
                uint32_t o = baddr_nt(0, GPITCH * 2, wn * 32 + p * 16, s, lane);
                ldmat4(bh[p], bBh + o);
                ldmat4(bl[p], bBl + o);
            }
#pragma unroll
            for (int mt = 0; mt < 2; mt++)
#pragma unroll
                for (int j = 0; j < 4; j++) {
                    const int p = j >> 1, h = (j & 1) * 2;
                    mma3(acc[mt][j], ah[mt], al[mt], bh[p][h], bh[p][h + 1], bl[p][h], bl[p][h + 1]);
                }
        }
    }

    const int gr = lane >> 2, gc = (lane & 3) * 2;
#pragma unroll
    for (int mt = 0; mt < 2; mt++)
#pragma unroll
        for (int j = 0; j < 4; j++) {
            int m = m0 + wm * 32 + mt * 16 + gr;
            int n = n0 + wn * 32 + j * 8 + gc;
            if (n < N) {
                if (!SPLIT) {
                    *(float2*)(C + (size_t)m * N + n)       = make_float2(acc[mt][j][0], acc[mt][j][1]);
                    *(float2*)(C + (size_t)(m + 8) * N + n) = make_float2(acc[mt][j][2], acc[mt][j][3]);
                } else {
                    __nv_bfloat16 h0, l0, h1, l1;
                    split2(acc[mt][j][0], h0, l0); split2(acc[mt][j][1], h1, l1);
                    *(__nv_bfloat162*)(Ch + (size_t)m * N + n) = __nv_bfloat162(h0, h1);
                    *(__nv_bfloat162*)(Cl + (size_t)m * N + n) = __nv_bfloat162(l0, l1);
                    split2(acc[mt][j][2], h0, l0); split2(acc[mt][j][3], h1, l1);
                    *(__nv_bfloat162*)(Ch + (size_t)(m + 8) * N + n) = __nv_bfloat162(h0, h1);
                    *(__nv_bfloat162*)(Cl + (size_t)(m + 8) * N + n) = __nv_bfloat162(l0, l1);
                }
            }
        }
}

// ---------------- Taylor features -> split bf16 [BH, T, DP] ----------------
__global__ void taylor_split(const float* __restrict__ src, int stride, int coloff,
                             __nv_bfloat16* __restrict__ dh, __nv_bfloat16* __restrict__ dl) {
    const int row = blockIdx.x * 8 + (threadIdx.x >> 5);   // [0, BH*TSEQ)
    const int lane = threadIdx.x & 31;
    const int bh = row / TSEQ, t = row % TSEQ;
    const int b = bh / NH, h = bh % NH;
    float qv = 0.f;
    if (lane < DK) qv = src[((size_t)b * TSEQ + t) * stride + coloff + h * DK + lane];
    __nv_bfloat16* oh = dh + (size_t)row * DP;
    __nv_bfloat16* ol = dl + (size_t)row * DP;
#pragma unroll
    for (int d0 = 0; d0 < DP; d0 += 32) {
        const int d = d0 + lane;
        int i_idx, j_idx;
        if (d >= 17) { int ij = d - 17; i_idx = (ij >> 4) & 15; j_idx = ij & 15; }
        else         { i_idx = (d - 1) & 15; j_idx = 0; }
        float qi = __shfl_sync(0xffffffffu, qv, i_idx);
        float qj = __shfl_sync(0xffffffffu, qv, j_idx);
        float val;
        if (d == 0) val = 1.f;
        else if (d < 1 + DK) val = qi * 0.5f;
        else if (d < DREAL) val = qi * qj * 0.17677669529663688f;
        else val = 0.f;
        __nv_bfloat16 hh, ll; split2(val, hh, ll);
        oh[d] = hh; ol[d] = ll;
    }
}

// ---- fused pass1+scan (HMMA): running state in registers, write exclusive Z split-bf16 ----
// One CTA per (dp-tile, bh); iterates the 16 chunks of its head sequentially.
#define P1KP 72
#define P1VP 136
__global__ void __launch_bounds__(256) pass1_scan_mma(
    const __nv_bfloat16* __restrict__ kfh, const __nv_bfloat16* __restrict__ kfl,
    const __nv_bfloat16* __restrict__ vh,  const __nv_bfloat16* __restrict__ vl,
    __nv_bfloat16* __restrict__ kvh, __nv_bfloat16* __restrict__ kvl) {
    __shared__ __nv_bfloat16 sk[2][32 * P1KP];
    __shared__ __nv_bfloat16 sv[2][32 * P1VP];
    const int bh = blockIdx.y, m0 = blockIdx.x * 64;
    const int b = bh / NH, h = bh % NH;
    const int tid = threadIdx.x, wid = tid >> 5, lane = tid & 31;
    const int wm = wid >> 2, wn = wid & 3;     // warp tile 32m x 32n over 64x128
    const int gr = lane >> 2, gc = (lane & 3) * 2;
    float acc[2][4][4] = {};                    // running state (inclusive of chunks < c)

    const uint32_t kb0 = smem_u32(sk[0]), kb1 = smem_u32(sk[1]);
    const uint32_t vb0 = smem_u32(sv[0]), vb1 = smem_u32(sv[1]);

    for (int c = 0; c < NCK; c++) {
        // write exclusive state Z_c = acc (before accumulating chunk c)
        const int chunk = bh * NCK + c;
#pragma unroll
        for (int mt = 0; mt < 2; mt++)
#pragma unroll
            for (int j = 0; j < 4; j++) {
                int m = m0 + wm * 32 + mt * 16 + gr;
                int n = wn * 32 + j * 8 + gc;
                size_t op = ((size_t)chunk * DP + m) * DV + n;
                __nv_bfloat16 h0, l0, h1, l1;
                split2(acc[mt][j][0], h0, l0); split2(acc[mt][j][1], h1, l1);
                *(__nv_bfloat162*)(kvh + op) = __nv_bfloat162(h0, h1);
                *(__nv_bfloat162*)(kvl + op) = __nv_bfloat162(l0, l1);
                split2(acc[mt][j][2], h0, l0); split2(acc[mt][j][3], h1, l1);
                *(__nv_bfloat162*)(kvh + op + 8 * DV) = __nv_bfloat162(h0, h1);
                *(__nv_bfloat162*)(kvl + op + 8 * DV) = __nv_bfloat162(l0, l1);
            }
        // accumulate chunk c: acc += kf_c^T @ v_c
        const int t0 = c * CHUNK;
        for (int tt = 0; tt < CHUNK; tt += 32) {
            {
                int r = tid >> 3, sg = tid & 7;
                size_t g = ((size_t)bh * TSEQ + t0 + tt + r) * DP + m0 + sg * 8;
                *(uint4*)&sk[0][r * P1KP + sg * 8] = *(const uint4*)(kfh + g);
                *(uint4*)&sk[1][r * P1KP + sg * 8] = *(const uint4*)(kfl + g);
            }
#pragma unroll
            for (int it = 0; it < 2; it++) {
                int idx = tid + it * 256;
                int r = idx >> 4, sg = idx & 15;
                size_t g = ((size_t)b * TSEQ + t0 + tt + r) * HID + h * DV + sg * 8;
                *(uint4*)&sv[0][r * P1VP + sg * 8] = *(const uint4*)(vh + g);
                *(uint4*)&sv[1][r * P1VP + sg * 8] = *(const uint4*)(vl + g);
            }
            __syncthreads();
#pragma unroll
            for (int s = 0; s < 32; s += 16) {
                uint32_t ah[2][4], al[2][4];
#pragma unroll
                for (int mt = 0; mt < 2; mt++) {
                    uint32_t o = aaddr_t(0, P1KP * 2, wm * 32 + mt * 16, s, lane);
                    ldmat4t(ah[mt], kb0 + o);
                    ldmat4t(al[mt], kb1 + o);
                }
                uint32_t bhf[2][4], blf[2][4];
#pragma unroll
                for (int p = 0; p < 2; p++) {
                    uint32_t o = baddr_t(0, P1VP * 2, wn * 32 + p * 16, s, lane);
                    ldmat4t(bhf[p], vb0 + o);
                    ldmat4t(blf[p], vb1 + o);
                }
#pragma unroll
                for (int mt = 0; mt < 2; mt++)
#pragma unroll
                    for (int j = 0; j < 4; j++) {
                        const int p = j >> 1, hs = (j & 1) * 2;
                        mma3(acc[mt][j], ah[mt], al[mt], bhf[p][hs], bhf[p][hs + 1], blf[p][hs], blf[p][hs + 1]);
                    }
            }
            __syncthreads();
        }
    }
}

// ---------------- per-chunk K1 = colsum(kf) ----------------
__global__ void k1_sum_kernel(const __nv_bfloat16* __restrict__ kfh,
                              const __nv_bfloat16* __restrict__ kfl,
                              float* __restrict__ k1) {
    int idx = blockIdx.x * 256 + threadIdx.x;
    if (idx >= NCH * DP) return;
    int chunk = idx / DP, d = idx % DP;
    int bh = chunk / NCK, c = chunk % NCK;
    size_t base = ((size_t)bh * TSEQ + c * CHUNK) * DP + d;
    float s = 0.f;
    for (int r = 0; r < CHUNK; r++) {
        size_t p = base + (size_t)r * DP;
        s += __bfloat162float(kfh[p]) + __bfloat162float(kfl[p]);
    }
    k1[idx] = s;
}

__global__ void scan_k1_kernel(float* __restrict__ k1) {
    int idx = blockIdx.x * 256 + threadIdx.x;
    if (idx >= BH * DP) return;
    int bh = idx / DP, d = idx % DP;
    float s = 0.f;
    for (int c = 0; c < NCK; c++) {
        size_t p = ((size_t)(bh * NCK + c)) * DP + d;
        float val = k1[p]; k1[p] = s; s += val;
    }
}

// ---------------- den inter: qf . Z1_exclusive ----------------
__global__ void den_inter_kernel(const __nv_bfloat16* __restrict__ qfh,
                                 const __nv_bfloat16* __restrict__ qfl,
                                 const float* __restrict__ k1,
                                 float* __restrict__ den) {
    int row = blockIdx.x * 8 + (threadIdx.x >> 5);
    int lane = threadIdx.x & 31;
    int bh = row / TSEQ, t = row % TSEQ;
    int chunk = bh * NCK + t / CHUNK;
    size_t qb = ((size_t)bh * TSEQ + t) * DP;
    const float* z = k1 + (size_t)chunk * DP;
    float s = 0.f;
    for (int d = lane; d < DP; d += 32)
        s += (__bfloat162float(qfh[qb + d]) + __bfloat162float(qfl[qb + d])) * z[d];
#pragma unroll
    for (int o = 16; o; o >>= 1) s += __shfl_xor_sync(0xffffffffu, s, o);
    if (lane == 0) den[row] = s;
}

// ---- fused inter+intra (HMMA): num = qf@Z (regs) ; S = tril(qf kf^T);
//      y_split = (num + S v)/den --------------------------------------------
#define ITP 40
#define ISP 136
#define I_SQ0 0
#define I_SQ1 (I_SQ0 + 128*ITP)
#define I_SK0 (I_SQ1 + 128*ITP)
#define I_SK1 (I_SK0 + 128*ITP)
#define I_SH  (I_SK1 + 128*ITP)
#define I_SL  (I_SH + 128*ISP)
#define I_SV0 (I_SL + 128*ISP)
#define I_SV1 (I_SV0 + 32*ISP)
#define I_END (I_SV1 + 32*ISP)
#define SMEM_INTRA (I_END * 2 + 512)

__global__ void __launch_bounds__(256) intra_mma(
    const __nv_bfloat16* __restrict__ qfh, const __nv_bfloat16* __restrict__ qfl,
    const __nv_bfloat16* __restrict__ kfh, const __nv_bfloat16* __restrict__ kfl,
    const __nv_bfloat16* __restrict__ zh,  const __nv_bfloat16* __restrict__ zl,
    const __nv_bfloat16* __restrict__ vh,  const __nv_bfloat16* __restrict__ vl,
    const float* __restrict__ denin,
    __nv_bfloat16* __restrict__ yh, __nv_bfloat16* __restrict__ yl) {
    extern __shared__ char dsm[];
    __nv_bfloat16* sm = (__nv_bfloat16*)dsm;
    float* dens = (float*)(dsm + I_END * 2);
    const uint32_t sb = smem_u32(sm);
    const int chunk = blockIdx.x;
    const int bh = chunk / NCK, c = chunk % NCK;
    const int b = bh / NH, h = bh % NH;
    const int t0 = c * CHUNK;
    const int tid = threadIdx.x, wid = tid >> 5, lane = tid & 31;
    const int wm = wid >> 2, wn = wid & 3;     // warp tile 64m x 32n
    const int gr = lane >> 2, gc = (lane & 3) * 2;

    // -------- phase 1: accS = qf @ kf^T  AND  accN = qf @ Z (shared a-frags) ----
    float accS[4][4][4] = {};
    float accN[4][4][4] = {};
    for (int kk = 0; kk < DP; kk += 32) {
#pragma unroll
        for (int it = 0; it < 2; it++) {
            int idx = tid + it * 256;
            int r = idx >> 2, sg = idx & 3;
            size_t gq = ((size_t)bh * TSEQ + t0 + r) * DP + kk + sg * 8;
            *(uint4*)&sm[I_SQ0 + r * ITP + sg * 8] = *(const uint4*)(qfh + gq);
            *(uint4*)&sm[I_SQ1 + r * ITP + sg * 8] = *(const uint4*)(qfl + gq);
            *(uint4*)&sm[I_SK0 + r * ITP + sg * 8] = *(const uint4*)(kfh + gq);
            *(uint4*)&sm[I_SK1 + r * ITP + sg * 8] = *(const uint4*)(kfl + gq);
        }
#pragma unroll
        for (int it = 0; it < 2; it++) {
            int idx = tid + it * 256;
            int r = idx >> 4, sg = idx & 15;
            size_t g = ((size_t)chunk * DP + kk + r) * DV + sg * 8;
            *(uint4*)&sm[I_SV0 + r * ISP + sg * 8] = *(const uint4*)(zh + g);
            *(uint4*)&sm[I_SV1 + r * ISP + sg * 8] = *(const uint4*)(zl + g);
        }
        __syncthreads();
#pragma unroll
        for (int s = 0; s < 32; s += 16) {
            uint32_t ah[4][4], al[4][4];
#pragma unroll
            for (int mt = 0; mt < 4; mt++) {
                uint32_t o = aaddr_nt(0, ITP * 2, wm * 64 + mt * 16, s, lane);
                ldmat4(ah[mt], sb + I_SQ0 * 2 + o);
                ldmat4(al[mt], sb + I_SQ1 * 2 + o);
            }
            {
                uint32_t bhf[2][4], blf[2][4];
#pragma unroll
                for (int p = 0; p < 2; p++) {
                    uint32_t o = baddr_nt(0, ITP * 2, wn * 32 + p * 16, s, lane);
                    ldmat4(bhf[p], sb + I_SK0 * 2 + o);
                    ldmat4(blf[p], sb + I_SK1 * 2 + o);
                }
#pragma unroll
                for (int mt = 0; mt < 4; mt++)
#pragma unroll
                    for (int j = 0; j < 4; j++) {
                        const int p = j >> 1, hs = (j & 1) * 2;
                        mma3(accS[mt][j], ah[mt], al[mt], bhf[p][hs], bhf[p][hs + 1], blf[p][hs], blf[p][hs + 1]);
                    }
            }
            {
                uint32_t bhf[2][4], blf[2][4];
#pragma unroll
                for (int p = 0; p < 2; p++) {
                    uint32_t o = baddr_t(0, ISP * 2, wn * 32 + p * 16, s, lane);
                    ldmat4t(bhf[p], sb + I_SV0 * 2 + o);
                    ldmat4t(blf[p], sb + I_SV1 * 2 + o);
                }
#pragma unroll
                for (int mt = 0; mt < 4; mt++)
#pragma unroll
                    for (int j = 0; j < 4; j++) {
                        const int p = j >> 1, hs = (j & 1) * 2;
                        mma3(accN[mt][j], ah[mt], al[mt], bhf[p][hs], bhf[p][hs + 1], blf[p][hs], blf[p][hs + 1]);
                    }
            }
        }
        __syncthreads();
    }

    // -------- mask + rowsum + split-store S --------
    if (tid < 128) dens[tid] = 0.f;
    __syncthreads();
#pragma unroll
    for (int mt = 0; mt < 4; mt++) {
        int mlo = wm * 64 + mt * 16 + gr, mhi = mlo + 8;
        float r0 = 0.f, r1 = 0.f;
#pragma unroll
        for (int j = 0; j < 4; j++) {
            int n = wn * 32 + j * 8 + gc;
            float v0 = (n     <= mlo) ? accS[mt][j][0] : 0.f;
            float v1 = (n + 1 <= mlo) ? accS[mt][j][1] : 0.f;
            float v2 = (n     <= mhi) ? accS[mt][j][2] : 0.f;
            float v3 = (n + 1 <= mhi) ? accS[mt][j][3] : 0.f;
            r0 += v0 + v1; r1 += v2 + v3;
            __nv_bfloat16 h0, l0, h1, l1;
            split2(v0, h0, l0); split2(v1, h1, l1);
            *(__nv_bfloat162*)&sm[I_SH + mlo * ISP + n] = __nv_bfloat162(h0, h1);
            *(__nv_bfloat162*)&sm[I_SL + mlo * ISP + n] = __nv_bfloat162(l0, l1);
            split2(v2, h0, l0); split2(v3, h1, l1);
            *(__nv_bfloat162*)&sm[I_SH + mhi * ISP + n] = __nv_bfloat162(h0, h1);
            *(__nv_bfloat162*)&sm[I_SL + mhi * ISP + n] = __nv_bfloat162(l0, l1);
        }
        r0 += __shfl_xor_sync(0xffffffffu, r0, 1);
        r0 += __shfl_xor_sync(0xffffffffu, r0, 2);
        r1 += __shfl_xor_sync(0xffffffffu, r1, 1);
        r1 += __shfl_xor_sync(0xffffffffu, r1, 2);
        if ((lane & 3) == 0) { atomicAdd(&dens[mlo], r0); atomicAdd(&dens[mhi], r1); }
    }
    __syncthreads();

    // -------- phase 2: acc2 = S @ v --------
    float acc2[4][4][4] = {};
    for (int ss = 0; ss < CHUNK; ss += 32) {
#pragma unroll
        for (int it = 0; it < 2; it++) {
            int idx = tid + it * 256;
            int r = idx >> 4, sg = idx & 15;
            size_t g = ((size_t)b * TSEQ + t0 + ss + r) * HID + h * DV + sg * 8;
            *(uint4*)&sm[I_SV0 + r * ISP + sg * 8] = *(const uint4*)(vh + g);
            *(uint4*)&sm[I_SV1 + r * ISP + sg * 8] = *(const uint4*)(vl + g);
        }
        __syncthreads();
#pragma unroll
        for (int s = 0; s < 32; s += 16) {
            uint32_t ah[4][4], al[4][4];
#pragma unroll
            for (int mt = 0; mt < 4; mt++) {
                uint32_t o = aaddr_nt(0, ISP * 2, wm * 64 + mt * 16, ss + s, lane);
                ldmat4(ah[mt], sb + I_SH * 2 + o);
                ldmat4(al[mt], sb + I_SL * 2 + o);
            }
            uint32_t bhf[2][4], blf[2][4];
#pragma unroll
            for (int p = 0; p < 2; p++) {
                uint32_t o = baddr_t(0, ISP * 2, wn * 32 + p * 16, s, lane);
                ldmat4t(bhf[p], sb + I_SV0 * 2 + o);
                ldmat4t(blf[p], sb + I_SV1 * 2 + o);
            }
#pragma unroll
            for (int mt = 0; mt < 4; mt++)
#pragma unroll
                for (int j = 0; j < 4; j++) {
                    const int p = j >> 1, hs = (j & 1) * 2;
                    mma3(acc2[mt][j], ah[mt], al[mt], bhf[p][hs], bhf[p][hs + 1], blf[p][hs], blf[p][hs + 1]);
                }
        }
        __syncthreads();
    }

    // -------- finalize: y = (accN + acc2)/den, write split-bf16 --------
#pragma unroll
    for (int mt = 0; mt < 4; mt++) {
        int mlo = wm * 64 + mt * 16 + gr, mhi = mlo + 8;
        int tlo = t0 + mlo, thi = t0 + mhi;
        float inv0 = 1.f / (denin[(size_t)bh * TSEQ + tlo] + dens[mlo] + EPSV);
        float inv1 = 1.f / (denin[(size_t)bh * TSEQ + thi] + dens[mhi] + EPSV);
#pragma unroll
        for (int j = 0; j < 4; j++) {
            int n = wn * 32 + j * 8 + gc;
            float y00 = (accN[mt][j][0] + acc2[mt][j][0]) * inv0;
            float y01 = (accN[mt][j][1] + acc2[mt][j][1]) * inv0;
            float y10 = (accN[mt][j][2] + acc2[mt][j][2]) * inv1;
            float y11 = (accN[mt][j][3] + acc2[mt][j][3]) * inv1;
            size_t o0 = ((size_t)b * TSEQ + tlo) * HID + h * DV + n;
            size_t o1 = ((size_t)b * TSEQ + thi) * HID + h * DV + n;
            __nv_bfloat16 h0, l0, h1, l1;
            split2(y00, h0, l0); split2(y01, h1, l1);
            *(__nv_bfloat162*)(yh + o0) = __nv_bfloat162(h0, h1);
            *(__nv_bfloat162*)(yl + o0) = __nv_bfloat162(l0, l1);
            split2(y10, h0, l0); split2(y11, h1, l1);
            *(__nv_bfloat162*)(yh + o1) = __nv_bfloat162(h0, h1);
            *(__nv_bfloat162*)(yl + o1) = __nv_bfloat162(l0, l1);
        }
    }
}

// ---------------- launch (stream-parallel DAG, capture-safe fork/join) ----------------
extern "C" void kernel_launch(void* const* d_in, const int* in_sizes, int n_in,
                              void* d_out, int out_size) {
    const float* x  = (const float*)d_in[0];
    const float* Wq = (const float*)d_in[1];
    const float* Wk = (const float*)d_in[2];
    const float* Wv = (const float*)d_in[3];
    const float* Wo = (const float*)d_in[4];
    float* out = (float*)d_out;

    float *pqk, *pk1, *pden;
    cudaGetSymbolAddress((void**)&pqk,  g_qk);
    cudaGetSymbolAddress((void**)&pk1,  g_k1);
    cudaGetSymbolAddress((void**)&pden, g_den);

    __nv_bfloat16 *xh, *xl, *yh, *yl, *vh, *vl, *qfh, *qfl, *kfh, *kfl, *kvh, *kvl;
    __nv_bfloat16 *wqkh, *wqkl, *wvh, *wvl, *woh, *wol;
    cudaGetSymbolAddress((void**)&xh, g_xh);   cudaGetSymbolAddress((void**)&xl, g_xl);
    cudaGetSymbolAddress((void**)&yh, g_yh);   cudaGetSymbolAddress((void**)&yl, g_yl);
    cudaGetSymbolAddress((void**)&vh, g_vh);   cudaGetSymbolAddress((void**)&vl, g_vl);
    cudaGetSymbolAddress((void**)&qfh, g_qfh); cudaGetSymbolAddress((void**)&qfl, g_qfl);
    cudaGetSymbolAddress((void**)&kfh, g_kfh); cudaGetSymbolAddress((void**)&kfl, g_kfl);
    cudaGetSymbolAddress((void**)&kvh, g_kvh); cudaGetSymbolAddress((void**)&kvl, g_kvl);
    cudaGetSymbolAddress((void**)&wqkh, g_wqkh); cudaGetSymbolAddress((void**)&wqkl, g_wqkl);
    cudaGetSymbolAddress((void**)&wvh, g_wvh); cudaGetSymbolAddress((void**)&wvl, g_wvl);
    cudaGetSymbolAddress((void**)&woh, g_woh); cudaGetSymbolAddress((void**)&wol, g_wol);

    cudaFuncSetAttribute(gemm_mma<false>, cudaFuncAttributeMaxDynamicSharedMemorySize, SMEM_MMA);
    cudaFuncSetAttribute(gemm_mma<true>,  cudaFuncAttributeMaxDynamicSharedMemorySize, SMEM_MMA);
    cudaFuncSetAttribute(intra_mma, cudaFuncAttributeMaxDynamicSharedMemorySize, SMEM_INTRA);

    static cudaStream_t s1 = nullptr, s2 = nullptr;
    static cudaEvent_t evB = nullptr, evX = nullptr, evWk = nullptr, evWv = nullptr,
                       evQ = nullptr, evK = nullptr, evDen = nullptr, evWo = nullptr;
    if (s1 == nullptr) {
        cudaStreamCreateWithFlags(&s1, cudaStreamNonBlocking);
        cudaStreamCreateWithFlags(&s2, cudaStreamNonBlocking);
        cudaEventCreateWithFlags(&evB,   cudaEventDisableTiming);
        cudaEventCreateWithFlags(&evX,   cudaEventDisableTiming);
        cudaEventCreateWithFlags(&evWk,  cudaEventDisableTiming);
        cudaEventCreateWithFlags(&evWv,  cudaEventDisableTiming);
        cudaEventCreateWithFlags(&evQ,   cudaEventDisableTiming);
        cudaEventCreateWithFlags(&evK,   cudaEventDisableTiming);
        cudaEventCreateWithFlags(&evDen, cudaEventDisableTiming);
        cudaEventCreateWithFlags(&evWo,  cudaEventDisableTiming);
    }

    // fork side streams from the (captured) default stream
    cudaEventRecord(evB, 0);
    cudaStreamWaitEvent(s1, evB, 0);
    cudaStreamWaitEvent(s2, evB, 0);

    // weight cvts off the critical path:
    // s1: Wq -> wqk rows [0,192);  s2: Wk -> rows [192,384), then Wv, then Wo
    cvt_split<<<(QKDIM * HID / 4) / 256, 256, 0, s1>>>(Wq, wqkh, wqkl, (size_t)QKDIM * HID);
    cvt_split<<<(QKDIM * HID / 4) / 256, 256, 0, s2>>>(
        Wk, wqkh + (size_t)QKDIM * HID, wqkl + (size_t)QKDIM * HID, (size_t)QKDIM * HID);
    cudaEventRecord(evWk, s2);
    cvt_split<<<(HID * HID / 4) / 256, 256, 0, s2>>>(Wv, wvh, wvl, (size_t)HID * HID);
    cudaEventRecord(evWv, s2);
    cvt_split<<<(HID * HID / 4) / 256, 256, 0, s2>>>(Wo, woh, wol, (size_t)HID * HID);
    cudaEventRecord(evWo, s2);

    // main stream: x cvt
    cvt_split<<<(BT * HID / 4) / 256, 256>>>(x, xh, xl, (size_t)BT * HID);
    cudaEventRecord(evX, 0);

    // s1: fused QK projection chain
    cudaStreamWaitEvent(s1, evX, 0);
    cudaStreamWaitEvent(s1, evWk, 0);
    gemm_mma<false><<<dim3(QK2 / 128, BT / 128), 512, SMEM_MMA, s1>>>(
        xh, xl, wqkh, wqkl, pqk, nullptr, nullptr, BT, QK2, HID);
    taylor_split<<<(BH * TSEQ) / 8, 256, 0, s1>>>(pqk, QK2, 0, qfh, qfl);
    cudaEventRecord(evQ, s1);
    taylor_split<<<(BH * TSEQ) / 8, 256, 0, s1>>>(pqk, QK2, QKDIM, kfh, kfl);
    cudaEventRecord(evK, s1);
    k1_sum_kernel<<<(NCH * DP) / 256, 256, 0, s1>>>(kfh, kfl, pk1);
    scan_k1_kernel<<<(BH * DP + 255) / 256, 256, 0, s1>>>(pk1);
    den_inter_kernel<<<(BH * TSEQ) / 8, 256, 0, s1>>>(qfh, qfl, pk1, pden);
    cudaEventRecord(evDen, s1);

    // main: V projection writing split bf16 directly (Wv cvt done on s2)
    cudaStreamWaitEvent(0, evWv, 0);
    gemm_mma<true><<<dim3(HID / 128, BT / 128), 512, SMEM_MMA>>>(
        xh, xl, wvh, wvl, nullptr, vh, vl, BT, HID, HID);

    // main: fused pass1+scan (needs kf) -> writes exclusive Z split-bf16 directly
    cudaStreamWaitEvent(0, evK, 0);
    pass1_scan_mma<<<dim3(DP / 64, BH), 256>>>(kfh, kfl, vh, vl, kvh, kvl);

    // main: fused inter+intra (needs qf, den)
    cudaStreamWaitEvent(0, evQ, 0);
    cudaStreamWaitEvent(0, evDen, 0);
    intra_mma<<<NCH, 256, SMEM_INTRA>>>(qfh, qfl, kfh, kfl, kvh, kvl, vh, vl, pden, yh, yl);

    // main: output projection (needs Wo cvt)
    cudaStreamWaitEvent(0, evWo, 0);
    gemm_mma<false><<<dim3(HID / 128, BT / 128), 512, SMEM_MMA>>>(
        yh, yl, woh, wol, out, nullptr, nullptr, BT, HID, HID);
}

// round 12
// speedup vs baseline: 1.1831x; 1.1831x over previous
#include <cuda_runtime.h>
#include <cuda_bf16.h>
#include <cstdint>

// ---------------- problem constants ----------------
#define BATCH  2
#define TSEQ   2048
#define BT     4096      // BATCH*TSEQ
#define HID    1536
#define NH     12
#define DK     16
#define DV     128
#define QKDIM  192       // NH*DK
#define QK2    384       // fused Q+K projection width
#define DREAL  273       // 1 + 16 + 256
#define DP     320       // padded feature dim
#define CHUNK  128
#define NCK    16        // TSEQ/CHUNK
#define BH     24        // BATCH*NH
#define NCH    384       // BH*NCK
#define EPSV   1e-12f

// ---------------- scratch (device globals, alloc-free) ----------------
__device__ float g_qk [(size_t)BT*QK2];
__device__ float g_kv [(size_t)NCH*DP*DV];
__device__ float g_k1 [(size_t)NCH*DP];
__device__ float g_den[(size_t)BH*TSEQ];

// bf16 split operands
__device__ __nv_bfloat16 g_xh [(size_t)BT*HID];
__device__ __nv_bfloat16 g_xl [(size_t)BT*HID];
__device__ __nv_bfloat16 g_yh [(size_t)BT*HID];
__device__ __nv_bfloat16 g_yl [(size_t)BT*HID];
__device__ __nv_bfloat16 g_vh [(size_t)BT*HID];
__device__ __nv_bfloat16 g_vl [(size_t)BT*HID];
__device__ __nv_bfloat16 g_qfh[(size_t)BH*TSEQ*DP];
__device__ __nv_bfloat16 g_qfl[(size_t)BH*TSEQ*DP];
__device__ __nv_bfloat16 g_kfh[(size_t)BH*TSEQ*DP];
__device__ __nv_bfloat16 g_kfl[(size_t)BH*TSEQ*DP];
__device__ __nv_bfloat16 g_kvh[(size_t)NCH*DP*DV];
__device__ __nv_bfloat16 g_kvl[(size_t)NCH*DP*DV];
__device__ __nv_bfloat16 g_wqkh[(size_t)QK2*HID];
__device__ __nv_bfloat16 g_wqkl[(size_t)QK2*HID];
__device__ __nv_bfloat16 g_wvh[(size_t)HID*HID];
__device__ __nv_bfloat16 g_wvl[(size_t)HID*HID];
__device__ __nv_bfloat16 g_woh[(size_t)HID*HID];
__device__ __nv_bfloat16 g_wol[(size_t)HID*HID];

// ---------------- helpers ----------------
__device__ __forceinline__ uint32_t smem_u32(const void* p) {
    uint32_t a;
    asm("{ .reg .u64 t; cvta.to.shared.u64 t, %1; cvt.u32.u64 %0, t; }" : "=r"(a) : "l"(p));
    return a;
}
__device__ __forceinline__ void cp_async16(uint32_t dst, const void* src) {
    asm volatile("cp.async.cg.shared.global [%0], [%1], 16;" :: "r"(dst), "l"(src));
}
#define CP_COMMIT() asm volatile("cp.async.commit_group;" ::: "memory")
#define CP_WAIT(N)  asm volatile("cp.async.wait_group %0;" :: "n"(N) : "memory")

__device__ __forceinline__ void ldmat4(uint32_t* r, uint32_t addr) {
    asm volatile("ldmatrix.sync.aligned.m8n8.x4.shared.b16 {%0,%1,%2,%3}, [%4];"
                 : "=r"(r[0]), "=r"(r[1]), "=r"(r[2]), "=r"(r[3]) : "r"(addr));
}
__device__ __forceinline__ void ldmat4t(uint32_t* r, uint32_t addr) {
    asm volatile("ldmatrix.sync.aligned.m8n8.x4.trans.shared.b16 {%0,%1,%2,%3}, [%4];"
                 : "=r"(r[0]), "=r"(r[1]), "=r"(r[2]), "=r"(r[3]) : "r"(addr));
}
__device__ __forceinline__ void mma_bf16(float* d,
                                         uint32_t a0, uint32_t a1, uint32_t a2, uint32_t a3,
                                         uint32_t b0, uint32_t b1) {
    asm volatile("mma.sync.aligned.m16n8k16.row.col.f32.bf16.bf16.f32 "
                 "{%0,%1,%2,%3}, {%4,%5,%6,%7}, {%8,%9}, {%0,%1,%2,%3};"
                 : "+f"(d[0]), "+f"(d[1]), "+f"(d[2]), "+f"(d[3])
                 : "r"(a0), "r"(a1), "r"(a2), "r"(a3), "r"(b0), "r"(b1));
}
// split-3 product: Ah*Bh + Ah*Bl + Al*Bh
__device__ __forceinline__ void mma3(float* d, const uint32_t* ah, const uint32_t* al,
                                     uint32_t bh0, uint32_t bh1, uint32_t bl0, uint32_t bl1) {
    mma_bf16(d, ah[0], ah[1], ah[2], ah[3], bh0, bh1);
    mma_bf16(d, ah[0], ah[1], ah[2], ah[3], bl0, bl1);
    mma_bf16(d, al[0], al[1], al[2], al[3], bh0, bh1);
}

// fragment address helpers (lane-dependent); pitchB = row pitch in bytes
__device__ __forceinline__ uint32_t aaddr_nt(uint32_t base, int pitchB, int m_off, int k_off, int lane) {
    int row = m_off + (lane & 7) + ((lane >> 3) & 1) * 8;
    int col = k_off + ((lane >> 4) & 1) * 8;
    return base + row * pitchB + col * 2;
}
__device__ __forceinline__ uint32_t aaddr_t(uint32_t base, int pitchB, int m_off, int k_off, int lane) {
    int row = k_off + (lane & 7) + ((lane >> 4) & 1) * 8;
    int col = m_off + ((lane >> 3) & 1) * 8;
    return base + row * pitchB + col * 2;
}
__device__ __forceinline__ uint32_t baddr_nt(uint32_t base, int pitchB, int n_off, int k_off, int lane) {
    int row = n_off + (lane & 7) + ((lane >> 4) & 1) * 8;
    int col = k_off + ((lane >> 3) & 1) * 8;
    return base + row * pitchB + col * 2;
}
__device__ __forceinline__ uint32_t baddr_t(uint32_t base, int pitchB, int n_off, int k_off, int lane) {
    int row = k_off + (lane & 7) + ((lane >> 3) & 1) * 8;
    int col = n_off + ((lane >> 4) & 1) * 8;
    return base + row * pitchB + col * 2;
}

__device__ __forceinline__ void split2(float v, __nv_bfloat16& h, __nv_bfloat16& l) {
    h = __float2bfloat16(v);
    l = __float2bfloat16(v - __bfloat162float(h));
}

// ---------------- split conversion fp32 -> (hi, lo) bf16 ----------------
__global__ void cvt_split(const float* __restrict__ x, __nv_bfloat16* __restrict__ hi,
                          __nv_bfloat16* __restrict__ lo, size_t n) {
    size_t i = ((size_t)blockIdx.x * 256 + threadIdx.x) * 4;
    if (i >= n) return;
    float4 v = *(const float4*)(x + i);
    float a[4] = {v.x, v.y, v.z, v.w};
    __nv_bfloat16 h[4], l[4];
#pragma unroll
    for (int j = 0; j < 4; j++) split2(a[j], h[j], l[j]);
    ((__nv_bfloat162*)(hi + i))[0] = __nv_bfloat162(h[0], h[1]);
    ((__nv_bfloat162*)(hi + i))[1] = __nv_bfloat162(h[2], h[3]);
    ((__nv_bfloat162*)(lo + i))[0] = __nv_bfloat162(l[0], l[1]);
    ((__nv_bfloat162*)(lo + i))[1] = __nv_bfloat162(l[2], l[3]);
}

// ---------------- HMMA split-bf16 GEMM: C[M,N] = A[M,K] @ B[N,K]^T ----------------
#define GPITCH 40
#define MAT_BYTES (128 * GPITCH * 2)
#define STAGE_BYTES (4 * MAT_BYTES)
#define NSTAGE 4
#define SMEM_MMA (NSTAGE * STAGE_BYTES)     // 163840

template <bool SPLIT>
__global__ void __launch_bounds__(512) gemm_mma(
    const __nv_bfloat16* __restrict__ Ahg, const __nv_bfloat16* __restrict__ Alg,
    const __nv_bfloat16* __restrict__ Bhg, const __nv_bfloat16* __restrict__ Blg,
    float* __restrict__ C, __nv_bfloat16* __restrict__ Ch, __nv_bfloat16* __restrict__ Cl,
    int M, int N, int K) {
    extern __shared__ char smem[];
    const uint32_t sb = smem_u32(smem);
    const int tid = threadIdx.x, wid = tid >> 5, lane = tid & 31;
    const int wm = wid >> 2, wn = wid & 3;           // 4x4 warps, 32x32 tiles
    const int m0 = blockIdx.y * 128, n0 = blockIdx.x * 128;
    const int nch = K / 32;

    float acc[2][4][4] = {};

    auto load_chunk = [&](int c, int s) {
        const uint32_t base = sb + (uint32_t)s * STAGE_BYTES;
        const int kk = c * 32;
#pragma unroll
        for (int it = 0; it < 4; it++) {
            int idx = tid + it * 512;
            int mat = idx >> 9;
            int r   = (idx >> 2) & 127;
            int seg = idx & 3;
            uint32_t dst = base + (uint32_t)mat * MAT_BYTES + (uint32_t)(r * (GPITCH * 2) + seg * 16);
            const __nv_bfloat16* src;
            if (mat < 2) {
                const __nv_bfloat16* A = (mat == 0) ? Ahg : Alg;
                src = A + (size_t)(m0 + r) * K + kk + seg * 8;
            } else {
                const __nv_bfloat16* B = (mat == 2) ? Bhg : Blg;
                int row = n0 + r; if (row >= N) row = N - 1;
                src = B + (size_t)row * K + kk + seg * 8;
            }
            cp_async16(dst, src);
        }
        CP_COMMIT();
    };

    {
        int pf = (nch < 3) ? nch : 3;
        for (int s = 0; s < pf; s++) load_chunk(s, s);
    }

    for (int c = 0; c < nch; c++) {
        int out = nch - c; if (out > 3) out = 3;
        if (out == 3)      CP_WAIT(2);
        else if (out == 2) CP_WAIT(1);
        else               CP_WAIT(0);
        __syncthreads();
        if (c + 3 < nch) load_chunk(c + 3, (c + 3) & (NSTAGE - 1));

        const uint32_t base = sb + (uint32_t)(c & (NSTAGE - 1)) * STAGE_BYTES;
        const uint32_t bAh = base, bAl = base + MAT_BYTES;
        const uint32_t bBh = base + 2 * MAT_BYTES, bBl = base + 3 * MAT_BYTES;
#pragma unroll
        for (int s = 0; s < 32; s += 16) {
            uint32_t ah[2][4], al[2][4];
#pragma unroll
            for (int mt = 0; mt < 2; mt++) {
                uint32_t o = aaddr_nt(0, GPITCH * 2, wm * 32 + mt * 16, s, lane);
                ldmat4(ah[mt], bAh + o);
                ldmat4(al[mt], bAl + o);
            }
            uint32_t bh[2][4], bl[2][4];
#pragma unroll
            for (int p = 0; p < 2; p++) {
                uint32_t o = baddr_nt(0, GPITCH * 2, wn * 32 + p * 16, s, lane);
                ldmat4(bh[p], bBh + o);
                ldmat4(bl[p], bBl + o);
            }
#pragma unroll
            for (int mt = 0; mt < 2; mt++)
#pragma unroll
                for (int j = 0; j < 4; j++) {
                    const int p = j >> 1, h = (j & 1) * 2;
                    mma3(acc[mt][j], ah[mt], al[mt], bh[p][h], bh[p][h + 1], bl[p][h], bl[p][h + 1]);
                }
        }
    }

    const int gr = lane >> 2, gc = (lane & 3) * 2;
#pragma unroll
    for (int mt = 0; mt < 2; mt++)
#pragma unroll
        for (int j = 0; j < 4; j++) {
            int m = m0 + wm * 32 + mt * 16 + gr;
            int n = n0 + wn * 32 + j * 8 + gc;
            if (n < N) {
                if (!SPLIT) {
                    *(float2*)(C + (size_t)m * N + n)       = make_float2(acc[mt][j][0], acc[mt][j][1]);
                    *(float2*)(C + (size_t)(m + 8) * N + n) = make_float2(acc[mt][j][2], acc[mt][j][3]);
                } else {
                    __nv_bfloat16 h0, l0, h1, l1;
                    split2(acc[mt][j][0], h0, l0); split2(acc[mt][j][1], h1, l1);
                    *(__nv_bfloat162*)(Ch + (size_t)m * N + n) = __nv_bfloat162(h0, h1);
                    *(__nv_bfloat162*)(Cl + (size_t)m * N + n) = __nv_bfloat162(l0, l1);
                    split2(acc[mt][j][2], h0, l0); split2(acc[mt][j][3], h1, l1);
                    *(__nv_bfloat162*)(Ch + (size_t)(m + 8) * N + n) = __nv_bfloat162(h0, h1);
                    *(__nv_bfloat162*)(Cl + (size_t)(m + 8) * N + n) = __nv_bfloat162(l0, l1);
                }
            }
        }
}

// ---------------- Taylor features -> split bf16 [BH, T, DP] ----------------
__global__ void taylor_split(const float* __restrict__ src, int stride, int coloff,
                             __nv_bfloat16* __restrict__ dh, __nv_bfloat16* __restrict__ dl) {
    const int row = blockIdx.x * 8 + (threadIdx.x >> 5);   // [0, BH*TSEQ)
    const int lane = threadIdx.x & 31;
    const int bh = row / TSEQ, t = row % TSEQ;
    const int b = bh / NH, h = bh % NH;
    float qv = 0.f;
    if (lane < DK) qv = src[((size_t)b * TSEQ + t) * stride + coloff + h * DK + lane];
    __nv_bfloat16* oh = dh + (size_t)row * DP;
    __nv_bfloat16* ol = dl + (size_t)row * DP;
#pragma unroll
    for (int d0 = 0; d0 < DP; d0 += 32) {
        const int d = d0 + lane;
        int i_idx, j_idx;
        if (d >= 17) { int ij = d - 17; i_idx = (ij >> 4) & 15; j_idx = ij & 15; }
        else         { i_idx = (d - 1) & 15; j_idx = 0; }
        float qi = __shfl_sync(0xffffffffu, qv, i_idx);
        float qj = __shfl_sync(0xffffffffu, qv, j_idx);
        float val;
        if (d == 0) val = 1.f;
        else if (d < 1 + DK) val = qi * 0.5f;
        else if (d < DREAL) val = qi * qj * 0.17677669529663688f;
        else val = 0.f;
        __nv_bfloat16 hh, ll; split2(val, hh, ll);
        oh[d] = hh; ol[d] = ll;
    }
}

// ---------------- pass1 (HMMA): KV[dp, dv] = kf^T @ v per chunk ----------------
#define P1KP 72
#define P1VP 136
__global__ void __launch_bounds__(256) pass1_mma(
    const __nv_bfloat16* __restrict__ kfh, const __nv_bfloat16* __restrict__ kfl,
    const __nv_bfloat16* __restrict__ vh,  const __nv_bfloat16* __restrict__ vl,
    float* __restrict__ kv) {
    __shared__ __nv_bfloat16 sk[2][32 * P1KP];
    __shared__ __nv_bfloat16 sv[2][32 * P1VP];
    const int chunk = blockIdx.y, m0 = blockIdx.x * 64;
    const int bh = chunk / NCK, c = chunk % NCK;
    const int b = bh / NH, h = bh % NH;
    const int t0 = c * CHUNK;
    const int tid = threadIdx.x, wid = tid >> 5, lane = tid & 31;
    const int wm = wid >> 2, wn = wid & 3;     // warp tile 32m x 32n
    float acc[2][4][4] = {};

    const uint32_t kb0 = smem_u32(sk[0]), kb1 = smem_u32(sk[1]);
    const uint32_t vb0 = smem_u32(sv[0]), vb1 = smem_u32(sv[1]);

    for (int tt = 0; tt < CHUNK; tt += 32) {
        {
            int r = tid >> 3, sg = tid & 7;
            size_t g = ((size_t)bh * TSEQ + t0 + tt + r) * DP + m0 + sg * 8;
            *(uint4*)&sk[0][r * P1KP + sg * 8] = *(const uint4*)(kfh + g);
            *(uint4*)&sk[1][r * P1KP + sg * 8] = *(const uint4*)(kfl + g);
        }
#pragma unroll
        for (int it = 0; it < 2; it++) {
            int idx = tid + it * 256;
            int r = idx >> 4, sg = idx & 15;
            size_t g = ((size_t)b * TSEQ + t0 + tt + r) * HID + h * DV + sg * 8;
            *(uint4*)&sv[0][r * P1VP + sg * 8] = *(const uint4*)(vh + g);
            *(uint4*)&sv[1][r * P1VP + sg * 8] = *(const uint4*)(vl + g);
        }
        __syncthreads();
#pragma unroll
        for (int s = 0; s < 32; s += 16) {
            uint32_t ah[2][4], al[2][4];
#pragma unroll
            for (int mt = 0; mt < 2; mt++) {
                uint32_t o = aaddr_t(0, P1KP * 2, wm * 32 + mt * 16, s, lane);
                ldmat4t(ah[mt], kb0 + o);
                ldmat4t(al[mt], kb1 + o);
            }
            uint32_t bhf[2][4], blf[2][4];
#pragma unroll
            for (int p = 0; p < 2; p++) {
                uint32_t o = baddr_t(0, P1VP * 2, wn * 32 + p * 16, s, lane);
                ldmat4t(bhf[p], vb0 + o);
                ldmat4t(blf[p], vb1 + o);
            }
#pragma unroll
            for (int mt = 0; mt < 2; mt++)
#pragma unroll
                for (int j = 0; j < 4; j++) {
                    const int p = j >> 1, hs = (j & 1) * 2;
                    mma3(acc[mt][j], ah[mt], al[mt], bhf[p][hs], bhf[p][hs + 1], blf[p][hs], blf[p][hs + 1]);
                }
        }
        __syncthreads();
    }
    const int gr = lane >> 2, gc = (lane & 3) * 2;
#pragma unroll
    for (int mt = 0; mt < 2; mt++)
#pragma unroll
        for (int j = 0; j < 4; j++) {
            int m = m0 + wm * 32 + mt * 16 + gr;
            int n = wn * 32 + j * 8 + gc;
            float* op = kv + ((size_t)chunk * DP + m) * DV + n;
            *(float2*)op             = make_float2(acc[mt][j][0], acc[mt][j][1]);
            *(float2*)(op + 8 * DV)  = make_float2(acc[mt][j][2], acc[mt][j][3]);
        }
}

// ---------------- per-chunk K1 = colsum(kf) ----------------
__global__ void k1_sum_kernel(const __nv_bfloat16* __restrict__ kfh,
                              const __nv_bfloat16* __restrict__ kfl,
                              float* __restrict__ k1) {
    int idx = blockIdx.x * 256 + threadIdx.x;
    if (idx >= NCH * DP) return;
    int chunk = idx / DP, d = idx % DP;
    int bh = chunk / NCK, c = chunk % NCK;
    size_t base = ((size_t)bh * TSEQ + c * CHUNK) * DP + d;
    float s = 0.f;
    for (int r = 0; r < CHUNK; r++) {
        size_t p = base + (size_t)r * DP;
        s += __bfloat162float(kfh[p]) + __bfloat162float(kfl[p]);
    }
    k1[idx] = s;
}

// ---------------- exclusive prefix scans over chunks ----------------
__global__ void scan_kv_kernel(const float* __restrict__ kv,
                               __nv_bfloat16* __restrict__ kvh,
                               __nv_bfloat16* __restrict__ kvl) {
    int idx = blockIdx.x * 256 + threadIdx.x;
    if (idx >= BH * DP * DV) return;
    int bh = idx / (DP * DV), de = idx % (DP * DV);
    float s = 0.f;
    for (int c = 0; c < NCK; c++) {
        size_t p = ((size_t)(bh * NCK + c)) * DP * DV + de;
        __nv_bfloat16 hh, ll; split2(s, hh, ll);
        kvh[p] = hh; kvl[p] = ll;
        s += kv[p];
    }
}
__global__ void scan_k1_kernel(float* __restrict__ k1) {
    int idx = blockIdx.x * 256 + threadIdx.x;
    if (idx >= BH * DP) return;
    int bh = idx / DP, d = idx % DP;
    float s = 0.f;
    for (int c = 0; c < NCK; c++) {
        size_t p = ((size_t)(bh * NCK + c)) * DP + d;
        float val = k1[p]; k1[p] = s; s += val;
    }
}

// ---------------- den inter: qf . Z1_exclusive ----------------
__global__ void den_inter_kernel(const __nv_bfloat16* __restrict__ qfh,
                                 const __nv_bfloat16* __restrict__ qfl,
                                 const float* __restrict__ k1,
                                 float* __restrict__ den) {
    int row = blockIdx.x * 8 + (threadIdx.x >> 5);
    int lane = threadIdx.x & 31;
    int bh = row / TSEQ, t = row % TSEQ;
    int chunk = bh * NCK + t / CHUNK;
    size_t qb = ((size_t)bh * TSEQ + t) * DP;
    const float* z = k1 + (size_t)chunk * DP;
    float s = 0.f;
    for (int d = lane; d < DP; d += 32)
        s += (__bfloat162float(qfh[qb + d]) + __bfloat162float(qfl[qb + d])) * z[d];
#pragma unroll
    for (int o = 16; o; o >>= 1) s += __shfl_xor_sync(0xffffffffu, s, o);
    if (lane == 0) den[row] = s;
}

// ---- fused inter+intra (HMMA): num = qf@Z (regs) ; S = tril(qf kf^T);
//      y_split = (num + S v)/den --------------------------------------------
#define ITP 40
#define ISP 136
#define I_SQ0 0
#define I_SQ1 (I_SQ0 + 128*ITP)
#define I_SK0 (I_SQ1 + 128*ITP)
#define I_SK1 (I_SK0 + 128*ITP)
#define I_SH  (I_SK1 + 128*ITP)
#define I_SL  (I_SH + 128*ISP)
#define I_SV0 (I_SL + 128*ISP)
#define I_SV1 (I_SV0 + 32*ISP)
#define I_END (I_SV1 + 32*ISP)
#define SMEM_INTRA (I_END * 2 + 512)

__global__ void __launch_bounds__(256) intra_mma(
    const __nv_bfloat16* __restrict__ qfh, const __nv_bfloat16* __restrict__ qfl,
    const __nv_bfloat16* __restrict__ kfh, const __nv_bfloat16* __restrict__ kfl,
    const __nv_bfloat16* __restrict__ zh,  const __nv_bfloat16* __restrict__ zl,
    const __nv_bfloat16* __restrict__ vh,  const __nv_bfloat16* __restrict__ vl,
    const float* __restrict__ denin,
    __nv_bfloat16* __restrict__ yh, __nv_bfloat16* __restrict__ yl) {
    extern __shared__ char dsm[];
    __nv_bfloat16* sm = (__nv_bfloat16*)dsm;
    float* dens = (float*)(dsm + I_END * 2);
    const uint32_t sb = smem_u32(sm);
    const int chunk = blockIdx.x;
    const int bh = chunk / NCK, c = chunk % NCK;
    const int b = bh / NH, h = bh % NH;
    const int t0 = c * CHUNK;
    const int tid = threadIdx.x, wid = tid >> 5, lane = tid & 31;
    const int wm = wid >> 2, wn = wid & 3;     // warp tile 64m x 32n
    const int gr = lane >> 2, gc = (lane & 3) * 2;

    // -------- phase 1: accS = qf @ kf^T  AND  accN = qf @ Z (shared a-frags) ----
    float accS[4][4][4] = {};
    float accN[4][4][4] = {};
    for (int kk = 0; kk < DP; kk += 32) {
#pragma unroll
        for (int it = 0; it < 2; it++) {
            int idx = tid + it * 256;
            int r = idx >> 2, sg = idx & 3;
            size_t gq = ((size_t)bh * TSEQ + t0 + r) * DP + kk + sg * 8;
            *(uint4*)&sm[I_SQ0 + r * ITP + sg * 8] = *(const uint4*)(qfh + gq);
            *(uint4*)&sm[I_SQ1 + r * ITP + sg * 8] = *(const uint4*)(qfl + gq);
            *(uint4*)&sm[I_SK0 + r * ITP + sg * 8] = *(const uint4*)(kfh + gq);
            *(uint4*)&sm[I_SK1 + r * ITP + sg * 8] = *(const uint4*)(kfl + gq);
        }
#pragma unroll
        for (int it = 0; it < 2; it++) {
            int idx = tid + it * 256;
            int r = idx >> 4, sg = idx & 15;
            size_t g = ((size_t)chunk * DP + kk + r) * DV + sg * 8;
            *(uint4*)&sm[I_SV0 + r * ISP + sg * 8] = *(const uint4*)(zh + g);
            *(uint4*)&sm[I_SV1 + r * ISP + sg * 8] = *(const uint4*)(zl + g);
        }
        __syncthreads();
#pragma unroll
        for (int s = 0; s < 32; s += 16) {
            uint32_t ah[4][4], al[4][4];
#pragma unroll
            for (int mt = 0; mt < 4; mt++) {
                uint32_t o = aaddr_nt(0, ITP * 2, wm * 64 + mt * 16, s, lane);
                ldmat4(ah[mt], sb + I_SQ0 * 2 + o);
                ldmat4(al[mt], sb + I_SQ1 * 2 + o);
            }
            {
                uint32_t bhf[2][4], blf[2][4];
#pragma unroll
                for (int p = 0; p < 2; p++) {
                    uint32_t o = baddr_nt(0, ITP * 2, wn * 32 + p * 16, s, lane);
                    ldmat4(bhf[p], sb + I_SK0 * 2 + o);
                    ldmat4(blf[p], sb + I_SK1 * 2 + o);
                }
#pragma unroll
                for (int mt = 0; mt < 4; mt++)
#pragma unroll
                    for (int j = 0; j < 4; j++) {
                        const int p = j >> 1, hs = (j & 1) * 2;
                        mma3(accS[mt][j], ah[mt], al[mt], bhf[p][hs], bhf[p][hs + 1], blf[p][hs], blf[p][hs + 1]);
                    }
            }
            {
                uint32_t bhf[2][4], blf[2][4];
#pragma unroll
                for (int p = 0; p < 2; p++) {
                    uint32_t o = baddr_t(0, ISP * 2, wn * 32 + p * 16, s, lane);
                    ldmat4t(bhf[p], sb + I_SV0 * 2 + o);
                    ldmat4t(blf[p], sb + I_SV1 * 2 + o);
                }
#pragma unroll
                for (int mt = 0; mt < 4; mt++)
#pragma unroll
                    for (int j = 0; j < 4; j++) {
                        const int p = j >> 1, hs = (j & 1) * 2;
                        mma3(accN[mt][j], ah[mt], al[mt], bhf[p][hs], bhf[p][hs + 1], blf[p][hs], blf[p][hs + 1]);
                    }
            }
        }
        __syncthreads();
    }

    // -------- mask + rowsum + split-store S --------
    if (tid < 128) dens[tid] = 0.f;
    __syncthreads();
#pragma unroll
    for (int mt = 0; mt < 4; mt++) {
        int mlo = wm * 64 + mt * 16 + gr, mhi = mlo + 8;
        float r0 = 0.f, r1 = 0.f;
#pragma unroll
        for (int j = 0; j < 4; j++) {
            int n = wn * 32 + j * 8 + gc;
            float v0 = (n     <= mlo) ? accS[mt][j][0] : 0.f;
            float v1 = (n + 1 <= mlo) ? accS[mt][j][1] : 0.f;
            float v2 = (n     <= mhi) ? accS[mt][j][2] : 0.f;
            float v3 = (n + 1 <= mhi) ? accS[mt][j][3] : 0.f;
            r0 += v0 + v1; r1 += v2 + v3;
            __nv_bfloat16 h0, l0, h1, l1;
            split2(v0, h0, l0); split2(v1, h1, l1);
            *(__nv_bfloat162*)&sm[I_SH + mlo * ISP + n] = __nv_bfloat162(h0, h1);
            *(__nv_bfloat162*)&sm[I_SL + mlo * ISP + n] = __nv_bfloat162(l0, l1);
            split2(v2, h0, l0); split2(v3, h1, l1);
            *(__nv_bfloat162*)&sm[I_SH + mhi * ISP + n] = __nv_bfloat162(h0, h1);
            *(__nv_bfloat162*)&sm[I_SL + mhi * ISP + n] = __nv_bfloat162(l0, l1);
        }
        r0 += __shfl_xor_sync(0xffffffffu, r0, 1);
        r0 += __shfl_xor_sync(0xffffffffu, r0, 2);
        r1 += __shfl_xor_sync(0xffffffffu, r1, 1);
        r1 += __shfl_xor_sync(0xffffffffu, r1, 2);
        if ((lane & 3) == 0) { atomicAdd(&dens[mlo], r0); atomicAdd(&dens[mhi], r1); }
    }
    __syncthreads();

    // -------- phase 2: acc2 = S @ v --------
    float acc2[4][4][4] = {};
    for (int ss = 0; ss < CHUNK; ss += 32) {
#pragma unroll
        for (int it = 0; it < 2; it++) {
            int idx = tid + it * 256;
            int r = idx >> 4, sg = idx & 15;
            size_t g = ((size_t)b * TSEQ + t0 + ss + r) * HID + h * DV + sg * 8;
            *(uint4*)&sm[I_SV0 + r * ISP + sg * 8] = *(const uint4*)(vh + g);
            *(uint4*)&sm[I_SV1 + r * ISP + sg * 8] = *(const uint4*)(vl + g);
        }
        __syncthreads();
#pragma unroll
        for (int s = 0; s < 32; s += 16) {
            uint32_t ah[4][4], al[4][4];
#pragma unroll
            for (int mt = 0; mt < 4; mt++) {
                uint32_t o = aaddr_nt(0, ISP * 2, wm * 64 + mt * 16, ss + s, lane);
                ldmat4(ah[mt], sb + I_SH * 2 + o);
                ldmat4(al[mt], sb + I_SL * 2 + o);
            }
            uint32_t bhf[2][4], blf[2][4];
#pragma unroll
            for (int p = 0; p < 2; p++) {
                uint32_t o = baddr_t(0, ISP * 2, wn * 32 + p * 16, s, lane);
                ldmat4t(bhf[p], sb + I_SV0 * 2 + o);
                ldmat4t(blf[p], sb + I_SV1 * 2 + o);
            }
#pragma unroll
            for (int mt = 0; mt < 4; mt++)
#pragma unroll
                for (int j = 0; j < 4; j++) {
                    const int p = j >> 1, hs = (j & 1) * 2;
                    mma3(acc2[mt][j], ah[mt], al[mt], bhf[p][hs], bhf[p][hs + 1], blf[p][hs], blf[p][hs + 1]);
                }
        }
        __syncthreads();
    }

    // -------- finalize: y = (accN + acc2)/den, write split-bf16 --------
#pragma unroll
    for (int mt = 0; mt < 4; mt++) {
        int mlo = wm * 64 + mt * 16 + gr, mhi = mlo + 8;
        int tlo = t0 + mlo, thi = t0 + mhi;
        float inv0 = 1.f / (denin[(size_t)bh * TSEQ + tlo] + dens[mlo] + EPSV);
        float inv1 = 1.f / (denin[(size_t)bh * TSEQ + thi] + dens[mhi] + EPSV);
#pragma unroll
        for (int j = 0; j < 4; j++) {
            int n = wn * 32 + j * 8 + gc;
            float y00 = (accN[mt][j][0] + acc2[mt][j][0]) * inv0;
            float y01 = (accN[mt][j][1] + acc2[mt][j][1]) * inv0;
            float y10 = (accN[mt][j][2] + acc2[mt][j][2]) * inv1;
            float y11 = (accN[mt][j][3] + acc2[mt][j][3]) * inv1;
            size_t o0 = ((size_t)b * TSEQ + tlo) * HID + h * DV + n;
            size_t o1 = ((size_t)b * TSEQ + thi) * HID + h * DV + n;
            __nv_bfloat16 h0, l0, h1, l1;
            split2(y00, h0, l0); split2(y01, h1, l1);
            *(__nv_bfloat162*)(yh + o0) = __nv_bfloat162(h0, h1);
            *(__nv_bfloat162*)(yl + o0) = __nv_bfloat162(l0, l1);
            split2(y10, h0, l0); split2(y11, h1, l1);
            *(__nv_bfloat162*)(yh + o1) = __nv_bfloat162(h0, h1);
            *(__nv_bfloat162*)(yl + o1) = __nv_bfloat162(l0, l1);
        }
    }
}

// ---------------- launch (stream-parallel DAG, capture-safe fork/join) ----------------
extern "C" void kernel_launch(void* const* d_in, const int* in_sizes, int n_in,
                              void* d_out, int out_size) {
    const float* x  = (const float*)d_in[0];
    const float* Wq = (const float*)d_in[1];
    const float* Wk = (const float*)d_in[2];
    const float* Wv = (const float*)d_in[3];
    const float* Wo = (const float*)d_in[4];
    float* out = (float*)d_out;

    float *pqk, *pkv, *pk1, *pden;
    cudaGetSymbolAddress((void**)&pqk,  g_qk);
    cudaGetSymbolAddress((void**)&pkv,  g_kv);
    cudaGetSymbolAddress((void**)&pk1,  g_k1);
    cudaGetSymbolAddress((void**)&pden, g_den);

    __nv_bfloat16 *xh, *xl, *yh, *yl, *vh, *vl, *qfh, *qfl, *kfh, *kfl, *kvh, *kvl;
    __nv_bfloat16 *wqkh, *wqkl, *wvh, *wvl, *woh, *wol;
    cudaGetSymbolAddress((void**)&xh, g_xh);   cudaGetSymbolAddress((void**)&xl, g_xl);
    cudaGetSymbolAddress((void**)&yh, g_yh);   cudaGetSymbolAddress((void**)&yl, g_yl);
    cudaGetSymbolAddress((void**)&vh, g_vh);   cudaGetSymbolAddress((void**)&vl, g_vl);
    cudaGetSymbolAddress((void**)&qfh, g_qfh); cudaGetSymbolAddress((void**)&qfl, g_qfl);
    cudaGetSymbolAddress((void**)&kfh, g_kfh); cudaGetSymbolAddress((void**)&kfl, g_kfl);
    cudaGetSymbolAddress((void**)&kvh, g_kvh); cudaGetSymbolAddress((void**)&kvl, g_kvl);
    cudaGetSymbolAddress((void**)&wqkh, g_wqkh); cudaGetSymbolAddress((void**)&wqkl, g_wqkl);
    cudaGetSymbolAddress((void**)&wvh, g_wvh); cudaGetSymbolAddress((void**)&wvl, g_wvl);
    cudaGetSymbolAddress((void**)&woh, g_woh); cudaGetSymbolAddress((void**)&wol, g_wol);

    cudaFuncSetAttribute(gemm_mma<false>, cudaFuncAttributeMaxDynamicSharedMemorySize, SMEM_MMA);
    cudaFuncSetAttribute(gemm_mma<true>,  cudaFuncAttributeMaxDynamicSharedMemorySize, SMEM_MMA);
    cudaFuncSetAttribute(intra_mma, cudaFuncAttributeMaxDynamicSharedMemorySize, SMEM_INTRA);

    static cudaStream_t s1 = nullptr, s2 = nullptr;
    static cudaEvent_t evB = nullptr, evX = nullptr, evWk = nullptr, evWv = nullptr,
                       evQ = nullptr, evK = nullptr, evDen = nullptr, evWo = nullptr;
    if (s1 == nullptr) {
        cudaStreamCreateWithFlags(&s1, cudaStreamNonBlocking);
        cudaStreamCreateWithFlags(&s2, cudaStreamNonBlocking);
        cudaEventCreateWithFlags(&evB,   cudaEventDisableTiming);
        cudaEventCreateWithFlags(&evX,   cudaEventDisableTiming);
        cudaEventCreateWithFlags(&evWk,  cudaEventDisableTiming);
        cudaEventCreateWithFlags(&evWv,  cudaEventDisableTiming);
        cudaEventCreateWithFlags(&evQ,   cudaEventDisableTiming);
        cudaEventCreateWithFlags(&evK,   cudaEventDisableTiming);
        cudaEventCreateWithFlags(&evDen, cudaEventDisableTiming);
        cudaEventCreateWithFlags(&evWo,  cudaEventDisableTiming);
    }

    // fork side streams from the (captured) default stream
    cudaEventRecord(evB, 0);
    cudaStreamWaitEvent(s1, evB, 0);
    cudaStreamWaitEvent(s2, evB, 0);

    // weight cvts off the critical path:
    // s1: Wq -> wqk rows [0,192);  s2: Wk -> rows [192,384), then Wv, then Wo
    cvt_split<<<(QKDIM * HID / 4) / 256, 256, 0, s1>>>(Wq, wqkh, wqkl, (size_t)QKDIM * HID);
    cvt_split<<<(QKDIM * HID / 4) / 256, 256, 0, s2>>>(
        Wk, wqkh + (size_t)QKDIM * HID, wqkl + (size_t)QKDIM * HID, (size_t)QKDIM * HID);
    cudaEventRecord(evWk, s2);
    cvt_split<<<(HID * HID / 4) / 256, 256, 0, s2>>>(Wv, wvh, wvl, (size_t)HID * HID);
    cudaEventRecord(evWv, s2);
    cvt_split<<<(HID * HID / 4) / 256, 256, 0, s2>>>(Wo, woh, wol, (size_t)HID * HID);
    cudaEventRecord(evWo, s2);

    // main stream: x cvt
    cvt_split<<<(BT * HID / 4) / 256, 256>>>(x, xh, xl, (size_t)BT * HID);
    cudaEventRecord(evX, 0);

    // s1: fused QK projection chain
    cudaStreamWaitEvent(s1, evX, 0);
    cudaStreamWaitEvent(s1, evWk, 0);
    gemm_mma<false><<<dim3(QK2 / 128, BT / 128), 512, SMEM_MMA, s1>>>(
        xh, xl, wqkh, wqkl, pqk, nullptr, nullptr, BT, QK2, HID);
    taylor_split<<<(BH * TSEQ) / 8, 256, 0, s1>>>(pqk, QK2, 0, qfh, qfl);
    cudaEventRecord(evQ, s1);
    taylor_split<<<(BH * TSEQ) / 8, 256, 0, s1>>>(pqk, QK2, QKDIM, kfh, kfl);
    cudaEventRecord(evK, s1);
    k1_sum_kernel<<<(NCH * DP) / 256, 256, 0, s1>>>(kfh, kfl, pk1);
    scan_k1_kernel<<<(BH * DP + 255) / 256, 256, 0, s1>>>(pk1);
    den_inter_kernel<<<(BH * TSEQ) / 8, 256, 0, s1>>>(qfh, qfl, pk1, pden);
    cudaEventRecord(evDen, s1);

    // main: V projection writing split bf16 directly (Wv cvt done on s2)
    cudaStreamWaitEvent(0, evWv, 0);
    gemm_mma<true><<<dim3(HID / 128, BT / 128), 512, SMEM_MMA>>>(
        xh, xl, wvh, wvl, nullptr, vh, vl, BT, HID, HID);

    // main: pass1 (1920 CTAs) -> fused scan+split (needs kf)
    cudaStreamWaitEvent(0, evK, 0);
    pass1_mma<<<dim3(DP / 64, NCH), 256>>>(kfh, kfl, vh, vl, pkv);
    scan_kv_kernel<<<(BH * DP * DV) / 256, 256>>>(pkv, kvh, kvl);

    // main: fused inter+intra (needs qf, den)
    cudaStreamWaitEvent(0, evQ, 0);
    cudaStreamWaitEvent(0, evDen, 0);
    intra_mma<<<NCH, 256, SMEM_INTRA>>>(qfh, qfl, kfh, kfl, kvh, kvl, vh, vl, pden, yh, yl);

    // main: output projection (needs Wo cvt)
    cudaStreamWaitEvent(0, evWo, 0);
    gemm_mma<false><<<dim3(HID / 128, BT / 128), 512, SMEM_MMA>>>(
        yh, yl, woh, wol, out, nullptr, nullptr, BT, HID, HID);
}

// round 13
// speedup vs baseline: 1.2962x; 1.0956x over previous
#include <cuda_runtime.h>
#include <cuda_bf16.h>
#include <cstdint>

// ---------------- problem constants ----------------
#define BATCH  2
#define TSEQ   2048
#define BT     4096      // BATCH*TSEQ
#define HID    1536
#define NH     12
#define DK     16
#define DV     128
#define QKDIM  192       // NH*DK
#define QK2    384       // fused Q+K projection width
#define DREAL  273       // 1 + 16 + 256
#define DP     320       // padded feature dim
#define CHUNK  128
#define NCK    16        // TSEQ/CHUNK
#define BH     24        // BATCH*NH
#define NCH    384       // BH*NCK
#define EPSV   1e-12f

// ---------------- scratch (device globals, alloc-free) ----------------
__device__ float g_qk [(size_t)BT*QK2];
__device__ float g_kv [(size_t)NCH*DP*DV];
__device__ float g_k1 [(size_t)NCH*DP];
__device__ float g_den[(size_t)BH*TSEQ];

// bf16 split operands
__device__ __nv_bfloat16 g_xh [(size_t)BT*HID];
__device__ __nv_bfloat16 g_xl [(size_t)BT*HID];
__device__ __nv_bfloat16 g_yh [(size_t)BT*HID];
__device__ __nv_bfloat16 g_yl [(size_t)BT*HID];
__device__ __nv_bfloat16 g_vh [(size_t)BT*HID];
__device__ __nv_bfloat16 g_vl [(size_t)BT*HID];
__device__ __nv_bfloat16 g_qfh[(size_t)BH*TSEQ*DP];
__device__ __nv_bfloat16 g_qfl[(size_t)BH*TSEQ*DP];
__device__ __nv_bfloat16 g_kfh[(size_t)BH*TSEQ*DP];
__device__ __nv_bfloat16 g_kfl[(size_t)BH*TSEQ*DP];
__device__ __nv_bfloat16 g_kvh[(size_t)NCH*DP*DV];
__device__ __nv_bfloat16 g_kvl[(size_t)NCH*DP*DV];
__device__ __nv_bfloat16 g_wqkh[(size_t)QK2*HID];
__device__ __nv_bfloat16 g_wqkl[(size_t)QK2*HID];
__device__ __nv_bfloat16 g_wvh[(size_t)HID*HID];
__device__ __nv_bfloat16 g_wvl[(size_t)HID*HID];
__device__ __nv_bfloat16 g_woh[(size_t)HID*HID];
__device__ __nv_bfloat16 g_wol[(size_t)HID*HID];

// ---------------- helpers ----------------
__device__ __forceinline__ uint32_t smem_u32(const void* p) {
    uint32_t a;
    asm("{ .reg .u64 t; cvta.to.shared.u64 t, %1; cvt.u32.u64 %0, t; }" : "=r"(a) : "l"(p));
    return a;
}
__device__ __forceinline__ void cp_async16(uint32_t dst, const void* src) {
    asm volatile("cp.async.cg.shared.global [%0], [%1], 16;" :: "r"(dst), "l"(src));
}
#define CP_COMMIT() asm volatile("cp.async.commit_group;" ::: "memory")
#define CP_WAIT(N)  asm volatile("cp.async.wait_group %0;" :: "n"(N) : "memory")

__device__ __forceinline__ void ldmat4(uint32_t* r, uint32_t addr) {
    asm volatile("ldmatrix.sync.aligned.m8n8.x4.shared.b16 {%0,%1,%2,%3}, [%4];"
                 : "=r"(r[0]), "=r"(r[1]), "=r"(r[2]), "=r"(r[3]) : "r"(addr));
}
__device__ __forceinline__ void ldmat4t(uint32_t* r, uint32_t addr) {
    asm volatile("ldmatrix.sync.aligned.m8n8.x4.trans.shared.b16 {%0,%1,%2,%3}, [%4];"
                 : "=r"(r[0]), "=r"(r[1]), "=r"(r[2]), "=r"(r[3]) : "r"(addr));
}
__device__ __forceinline__ void mma_bf16(float* d,
                                         uint32_t a0, uint32_t a1, uint32_t a2, uint32_t a3,
                                         uint32_t b0, uint32_t b1) {
    asm volatile("mma.sync.aligned.m16n8k16.row.col.f32.bf16.bf16.f32 "
                 "{%0,%1,%2,%3}, {%4,%5,%6,%7}, {%8,%9}, {%0,%1,%2,%3};"
                 : "+f"(d[0]), "+f"(d[1]), "+f"(d[2]), "+f"(d[3])
                 : "r"(a0), "r"(a1), "r"(a2), "r"(a3), "r"(b0), "r"(b1));
}
// split-3 product: Ah*Bh + Ah*Bl + Al*Bh
__device__ __forceinline__ void mma3(float* d, const uint32_t* ah, const uint32_t* al,
                                     uint32_t bh0, uint32_t bh1, uint32_t bl0, uint32_t bl1) {
    mma_bf16(d, ah[0], ah[1], ah[2], ah[3], bh0, bh1);
    mma_bf16(d, ah[0], ah[1], ah[2], ah[3], bl0, bl1);
    mma_bf16(d, al[0], al[1], al[2], al[3], bh0, bh1);
}

// fragment address helpers (lane-dependent); pitchB = row pitch in bytes
__device__ __forceinline__ uint32_t aaddr_nt(uint32_t base, int pitchB, int m_off, int k_off, int lane) {
    int row = m_off + (lane & 7) + ((lane >> 3) & 1) * 8;
    int col = k_off + ((lane >> 4) & 1) * 8;
    return base + row * pitchB + col * 2;
}
__device__ __forceinline__ uint32_t aaddr_t(uint32_t base, int pitchB, int m_off, int k_off, int lane) {
    int row = k_off + (lane & 7) + ((lane >> 4) & 1) * 8;
    int col = m_off + ((lane >> 3) & 1) * 8;
    return base + row * pitchB + col * 2;
}
__device__ __forceinline__ uint32_t baddr_nt(uint32_t base, int pitchB, int n_off, int k_off, int lane) {
    int row = n_off + (lane & 7) + ((lane >> 4) & 1) * 8;
    int col = k_off + ((lane >> 3) & 1) * 8;
    return base + row * pitchB + col * 2;
}
__device__ __forceinline__ uint32_t baddr_t(uint32_t base, int pitchB, int n_off, int k_off, int lane) {
    int row = k_off + (lane & 7) + ((lane >> 3) & 1) * 8;
    int col = n_off + ((lane >> 4) & 1) * 8;
    return base + row * pitchB + col * 2;
}

__device__ __forceinline__ void split2(float v, __nv_bfloat16& h, __nv_bfloat16& l) {
    h = __float2bfloat16(v);
    l = __float2bfloat16(v - __bfloat162float(h));
}

// ---------------- split conversion fp32 -> (hi, lo) bf16 ----------------
__global__ void cvt_split(const float* __restrict__ x, __nv_bfloat16* __restrict__ hi,
                          __nv_bfloat16* __restrict__ lo, size_t n) {
    size_t i = ((size_t)blockIdx.x * 256 + threadIdx.x) * 4;
    if (i >= n) return;
    float4 v = *(const float4*)(x + i);
    float a[4] = {v.x, v.y, v.z, v.w};
    __nv_bfloat16 h[4], l[4];
#pragma unroll
    for (int j = 0; j < 4; j++) split2(a[j], h[j], l[j]);
    ((__nv_bfloat162*)(hi + i))[0] = __nv_bfloat162(h[0], h[1]);
    ((__nv_bfloat162*)(hi + i))[1] = __nv_bfloat162(h[2], h[3]);
    ((__nv_bfloat162*)(lo + i))[0] = __nv_bfloat162(l[0], l[1]);
    ((__nv_bfloat162*)(lo + i))[1] = __nv_bfloat162(l[2], l[3]);
}

// ---------------- HMMA split-bf16 GEMM: C[M,N] = A[M,K] @ B[N,K]^T ----------------
// 512 threads (4x4 warps, 32x32 warp tiles), K-chunk 64, 2-stage cp.async ring.
#define GPITCH 72
#define MAT_BYTES (128 * GPITCH * 2)        // 18432
#define STAGE_BYTES (4 * MAT_BYTES)         // 73728
#define SMEM_MMA (2 * STAGE_BYTES)          // 147456

template <bool SPLIT>
__global__ void __launch_bounds__(512) gemm_mma(
    const __nv_bfloat16* __restrict__ Ahg, const __nv_bfloat16* __restrict__ Alg,
    const __nv_bfloat16* __restrict__ Bhg, const __nv_bfloat16* __restrict__ Blg,
    float* __restrict__ C, __nv_bfloat16* __restrict__ Ch, __nv_bfloat16* __restrict__ Cl,
    int M, int N, int K) {
    extern __shared__ char smem[];
    const uint32_t sb = smem_u32(smem);
    const int tid = threadIdx.x, wid = tid >> 5, lane = tid & 31;
    const int wm = wid >> 2, wn = wid & 3;           // 4x4 warps, 32x32 tiles
    const int m0 = blockIdx.y * 128, n0 = blockIdx.x * 128;
    const int nch = K / 64;

    float acc[2][4][4] = {};

    auto load_chunk = [&](int c, int s) {
        const uint32_t base = sb + (uint32_t)s * STAGE_BYTES;
        const int kk = c * 64;
#pragma unroll
        for (int it = 0; it < 8; it++) {
            int idx = tid + it * 512;                // 0..4095
            int mat = idx >> 10;                     // 0..3 (1024 per mat)
            int r   = (idx >> 3) & 127;
            int seg = idx & 7;
            uint32_t dst = base + (uint32_t)mat * MAT_BYTES + (uint32_t)(r * (GPITCH * 2) + seg * 16);
            const __nv_bfloat16* src;
            if (mat < 2) {
                const __nv_bfloat16* A = (mat == 0) ? Ahg : Alg;
                src = A + (size_t)(m0 + r) * K + kk + seg * 8;
            } else {
                const __nv_bfloat16* B = (mat == 2) ? Bhg : Blg;
                src = B + (size_t)(n0 + r) * K + kk + seg * 8;
            }
            cp_async16(dst, src);
        }
        CP_COMMIT();
    };

    load_chunk(0, 0);

    for (int c = 0; c < nch; c++) {
        CP_WAIT(0);                                   // chunk c data arrived
        __syncthreads();                              // all warps past stage (c+1)&1 reads
        if (c + 1 < nch) load_chunk(c + 1, (c + 1) & 1);

        const uint32_t base = sb + (uint32_t)(c & 1) * STAGE_BYTES;
        const uint32_t bAh = base, bAl = base + MAT_BYTES;
        const uint32_t bBh = base + 2 * MAT_BYTES, bBl = base + 3 * MAT_BYTES;
#pragma unroll
        for (int s = 0; s < 64; s += 16) {
            uint32_t ah[2][4], al[2][4];
#pragma unroll
            for (int mt = 0; mt < 2; mt++) {
                uint32_t o = aaddr_nt(0, GPITCH * 2, wm * 32 + mt * 16, s, lane);
                ldmat4(ah[mt], bAh + o);
                ldmat4(al[mt], bAl + o);
            }
            uint32_t bh[2][4], bl[2][4];
#pragma unroll
            for (int p = 0; p < 2; p++) {
                uint32_t o = baddr_nt(0, GPITCH * 2, wn * 32 + p * 16, s, lane);
                ldmat4(bh[p], bBh + o);
                ldmat4(bl[p], bBl + o);
            }
#pragma unroll
            for (int mt = 0; mt < 2; mt++)
#pragma unroll
                for (int j = 0; j < 4; j++) {
                    const int p = j >> 1, h = (j & 1) * 2;
                    mma3(acc[mt][j], ah[mt], al[mt], bh[p][h], bh[p][h + 1], bl[p][h], bl[p][h + 1]);
                }
        }
    }

    const int gr = lane >> 2, gc = (lane & 3) * 2;
#pragma unroll
    for (int mt = 0; mt < 2; mt++)
#pragma unroll
        for (int j = 0; j < 4; j++) {
            int m = m0 + wm * 32 + mt * 16 + gr;
            int n = n0 + wn * 32 + j * 8 + gc;
            if (n < N) {
                if (!SPLIT) {
                    *(float2*)(C + (size_t)m * N + n)       = make_float2(acc[mt][j][0], acc[mt][j][1]);
                    *(float2*)(C + (size_t)(m + 8) * N + n) = make_float2(acc[mt][j][2], acc[mt][j][3]);
                } else {
                    __nv_bfloat16 h0, l0, h1, l1;
                    split2(acc[mt][j][0], h0, l0); split2(acc[mt][j][1], h1, l1);
                    *(__nv_bfloat162*)(Ch + (size_t)m * N + n) = __nv_bfloat162(h0, h1);
                    *(__nv_bfloat162*)(Cl + (size_t)m * N + n) = __nv_bfloat162(l0, l1);
                    split2(acc[mt][j][2], h0, l0); split2(acc[mt][j][3], h1, l1);
                    *(__nv_bfloat162*)(Ch + (size_t)(m + 8) * N + n) = __nv_bfloat162(h0, h1);
                    *(__nv_bfloat162*)(Cl + (size_t)(m + 8) * N + n) = __nv_bfloat162(l0, l1);
                }
            }
        }
}

// ---------------- Taylor features -> split bf16 [BH, T, DP] ----------------
__global__ void taylor_split(const float* __restrict__ src, int stride, int coloff,
                             __nv_bfloat16* __restrict__ dh, __nv_bfloat16* __restrict__ dl) {
    const int row = blockIdx.x * 8 + (threadIdx.x >> 5);   // [0, BH*TSEQ)
    const int lane = threadIdx.x & 31;
    const int bh = row / TSEQ, t = row % TSEQ;
    const int b = bh / NH, h = bh % NH;
    float qv = 0.f;
    if (lane < DK) qv = src[((size_t)b * TSEQ + t) * stride + coloff + h * DK + lane];
    __nv_bfloat16* oh = dh + (size_t)row * DP;
    __nv_bfloat16* ol = dl + (size_t)row * DP;
#pragma unroll
    for (int d0 = 0; d0 < DP; d0 += 32) {
        const int d = d0 + lane;
        int i_idx, j_idx;
        if (d >= 17) { int ij = d - 17; i_idx = (ij >> 4) & 15; j_idx = ij & 15; }
        else         { i_idx = (d - 1) & 15; j_idx = 0; }
        float qi = __shfl_sync(0xffffffffu, qv, i_idx);
        float qj = __shfl_sync(0xffffffffu, qv, j_idx);
        float val;
        if (d == 0) val = 1.f;
        else if (d < 1 + DK) val = qi * 0.5f;
        else if (d < DREAL) val = qi * qj * 0.17677669529663688f;
        else val = 0.f;
        __nv_bfloat16 hh, ll; split2(val, hh, ll);
        oh[d] = hh; ol[d] = ll;
    }
}

// ---------------- pass1 (HMMA): KV[dp, dv] = kf^T @ v per chunk ----------------
#define P1KP 72
#define P1VP 136
__global__ void __launch_bounds__(256) pass1_mma(
    const __nv_bfloat16* __restrict__ kfh, const __nv_bfloat16* __restrict__ kfl,
    const __nv_bfloat16* __restrict__ vh,  const __nv_bfloat16* __restrict__ vl,
    float* __restrict__ kv) {
    __shared__ __nv_bfloat16 sk[2][32 * P1KP];
    __shared__ __nv_bfloat16 sv[2][32 * P1VP];
    const int chunk = blockIdx.y, m0 = blockIdx.x * 64;
    const int bh = chunk / NCK, c = chunk % NCK;
    const int b = bh / NH, h = bh % NH;
    const int t0 = c * CHUNK;
    const int tid = threadIdx.x, wid = tid >> 5, lane = tid & 31;
    const int wm = wid >> 2, wn = wid & 3;     // warp tile 32m x 32n
    float acc[2][4][4] = {};

    const uint32_t kb0 = smem_u32(sk[0]), kb1 = smem_u32(sk[1]);
    const uint32_t vb0 = smem_u32(sv[0]), vb1 = smem_u32(sv[1]);

    for (int tt = 0; tt < CHUNK; tt += 32) {
        {
            int r = tid >> 3, sg = tid & 7;
            size_t g = ((size_t)bh * TSEQ + t0 + tt + r) * DP + m0 + sg * 8;
            *(uint4*)&sk[0][r * P1KP + sg * 8] = *(const uint4*)(kfh + g);
            *(uint4*)&sk[1][r * P1KP + sg * 8] = *(const uint4*)(kfl + g);
        }
#pragma unroll
        for (int it = 0; it < 2; it++) {
            int idx = tid + it * 256;
            int r = idx >> 4, sg = idx & 15;
            size_t g = ((size_t)b * TSEQ + t0 + tt + r) * HID + h * DV + sg * 8;
            *(uint4*)&sv[0][r * P1VP + sg * 8] = *(const uint4*)(vh + g);
            *(uint4*)&sv[1][r * P1VP + sg * 8] = *(const uint4*)(vl + g);
        }
        __syncthreads();
#pragma unroll
        for (int s = 0; s < 32; s += 16) {
            uint32_t ah[2][4], al[2][4];
#pragma unroll
            for (int mt = 0; mt < 2; mt++) {
                uint32_t o = aaddr_t(0, P1KP * 2, wm * 32 + mt * 16, s, lane);
                ldmat4t(ah[mt], kb0 + o);
                ldmat4t(al[mt], kb1 + o);
            }
            uint32_t bhf[2][4], blf[2][4];
#pragma unroll
            for (int p = 0; p < 2; p++) {
                uint32_t o = baddr_t(0, P1VP * 2, wn * 32 + p * 16, s, lane);
                ldmat4t(bhf[p], vb0 + o);
                ldmat4t(blf[p], vb1 + o);
            }
#pragma unroll
            for (int mt = 0; mt < 2; mt++)
#pragma unroll
                for (int j = 0; j < 4; j++) {
                    const int p = j >> 1, hs = (j & 1) * 2;
                    mma3(acc[mt][j], ah[mt], al[mt], bhf[p][hs], bhf[p][hs + 1], blf[p][hs], blf[p][hs + 1]);
                }
        }
        __syncthreads();
    }
    const int gr = lane >> 2, gc = (lane & 3) * 2;
#pragma unroll
    for (int mt = 0; mt < 2; mt++)
#pragma unroll
        for (int j = 0; j < 4; j++) {
            int m = m0 + wm * 32 + mt * 16 + gr;
            int n = wn * 32 + j * 8 + gc;
            float* op = kv + ((size_t)chunk * DP + m) * DV + n;
            *(float2*)op             = make_float2(acc[mt][j][0], acc[mt][j][1]);
            *(float2*)(op + 8 * DV)  = make_float2(acc[mt][j][2], acc[mt][j][3]);
        }
}

// ---------------- per-chunk K1 = colsum(kf) ----------------
__global__ void k1_sum_kernel(const __nv_bfloat16* __restrict__ kfh,
                              const __nv_bfloat16* __restrict__ kfl,
                              float* __restrict__ k1) {
    int idx = blockIdx.x * 256 + threadIdx.x;
    if (idx >= NCH * DP) return;
    int chunk = idx / DP, d = idx % DP;
    int bh = chunk / NCK, c = chunk % NCK;
    size_t base = ((size_t)bh * TSEQ + c * CHUNK) * DP + d;
    float s = 0.f;
    for (int r = 0; r < CHUNK; r++) {
        size_t p = base + (size_t)r * DP;
        s += __bfloat162float(kfh[p]) + __bfloat162float(kfl[p]);
    }
    k1[idx] = s;
}

// ---------------- exclusive prefix scans over chunks ----------------
__global__ void scan_kv_kernel(const float* __restrict__ kv,
                               __nv_bfloat16* __restrict__ kvh,
                               __nv_bfloat16* __restrict__ kvl) {
    int idx = blockIdx.x * 256 + threadIdx.x;
    if (idx >= BH * DP * DV) return;
    int bh = idx / (DP * DV), de = idx % (DP * DV);
    float s = 0.f;
    for (int c = 0; c < NCK; c++) {
        size_t p = ((size_t)(bh * NCK + c)) * DP * DV + de;
        __nv_bfloat16 hh, ll; split2(s, hh, ll);
        kvh[p] = hh; kvl[p] = ll;
        s += kv[p];
    }
}
__global__ void scan_k1_kernel(float* __restrict__ k1) {
    int idx = blockIdx.x * 256 + threadIdx.x;
    if (idx >= BH * DP) return;
    int bh = idx / DP, d = idx % DP;
    float s = 0.f;
    for (int c = 0; c < NCK; c++) {
        size_t p = ((size_t)(bh * NCK + c)) * DP + d;
        float val = k1[p]; k1[p] = s; s += val;
    }
}

// ---------------- den inter: qf . Z1_exclusive ----------------
__global__ void den_inter_kernel(const __nv_bfloat16* __restrict__ qfh,
                                 const __nv_bfloat16* __restrict__ qfl,
                                 const float* __restrict__ k1,
                                 float* __restrict__ den) {
    int row = blockIdx.x * 8 + (threadIdx.x >> 5);
    int lane = threadIdx.x & 31;
    int bh = row / TSEQ, t = row % TSEQ;
    int chunk = bh * NCK + t / CHUNK;
    size_t qb = ((size_t)bh * TSEQ + t) * DP;
    const float* z = k1 + (size_t)chunk * DP;
    float s = 0.f;
    for (int d = lane; d < DP; d += 32)
        s += (__bfloat162float(qfh[qb + d]) + __bfloat162float(qfl[qb + d])) * z[d];
#pragma unroll
    for (int o = 16; o; o >>= 1) s += __shfl_xor_sync(0xffffffffu, s, o);
    if (lane == 0) den[row] = s;
}

// ---- fused inter+intra (HMMA): num = qf@Z (regs) ; S = tril(qf kf^T);
//      y_split = (num + S v)/den --------------------------------------------
#define ITP 40
#define ISP 136
#define I_SQ0 0
#define I_SQ1 (I_SQ0 + 128*ITP)
#define I_SK0 (I_SQ1 + 128*ITP)
#define I_SK1 (I_SK0 + 128*ITP)
#define I_SH  (I_SK1 + 128*ITP)
#define I_SL  (I_SH + 128*ISP)
#define I_SV0 (I_SL + 128*ISP)
#define I_SV1 (I_SV0 + 32*ISP)
#define I_END (I_SV1 + 32*ISP)
#define SMEM_INTRA (I_END * 2 + 512)

__global__ void __launch_bounds__(256) intra_mma(
    const __nv_bfloat16* __restrict__ qfh, const __nv_bfloat16* __restrict__ qfl,
    const __nv_bfloat16* __restrict__ kfh, const __nv_bfloat16* __restrict__ kfl,
    const __nv_bfloat16* __restrict__ zh,  const __nv_bfloat16* __restrict__ zl,
    const __nv_bfloat16* __restrict__ vh,  const __nv_bfloat16* __restrict__ vl,
    const float* __restrict__ denin,
    __nv_bfloat16* __restrict__ yh, __nv_bfloat16* __restrict__ yl) {
    extern __shared__ char dsm[];
    __nv_bfloat16* sm = (__nv_bfloat16*)dsm;
    float* dens = (float*)(dsm + I_END * 2);
    const uint32_t sb = smem_u32(sm);
    const int chunk = blockIdx.x;
    const int bh = chunk / NCK, c = chunk % NCK;
    const int b = bh / NH, h = bh % NH;
    const int t0 = c * CHUNK;
    const int tid = threadIdx.x, wid = tid >> 5, lane = tid & 31;
    const int wm = wid >> 2, wn = wid & 3;     // warp tile 64m x 32n
    const int gr = lane >> 2, gc = (lane & 3) * 2;

    // -------- phase 1: accS = qf @ kf^T  AND  accN = qf @ Z (shared a-frags) ----
    float accS[4][4][4] = {};
    float accN[4][4][4] = {};
    for (int kk = 0; kk < DP; kk += 32) {
#pragma unroll
        for (int it = 0; it < 2; it++) {
            int idx = tid + it * 256;
            int r = idx >> 2, sg = idx & 3;
            size_t gq = ((size_t)bh * TSEQ + t0 + r) * DP + kk + sg * 8;
            *(uint4*)&sm[I_SQ0 + r * ITP + sg * 8] = *(const uint4*)(qfh + gq);
            *(uint4*)&sm[I_SQ1 + r * ITP + sg * 8] = *(const uint4*)(qfl + gq);
            *(uint4*)&sm[I_SK0 + r * ITP + sg * 8] = *(const uint4*)(kfh + gq);
            *(uint4*)&sm[I_SK1 + r * ITP + sg * 8] = *(const uint4*)(kfl + gq);
        }
#pragma unroll
        for (int it = 0; it < 2; it++) {
            int idx = tid + it * 256;
            int r = idx >> 4, sg = idx & 15;
            size_t g = ((size_t)chunk * DP + kk + r) * DV + sg * 8;
            *(uint4*)&sm[I_SV0 + r * ISP + sg * 8] = *(const uint4*)(zh + g);
            *(uint4*)&sm[I_SV1 + r * ISP + sg * 8] = *(const uint4*)(zl + g);
        }
        __syncthreads();
#pragma unroll
        for (int s = 0; s < 32; s += 16) {
            uint32_t ah[4][4], al[4][4];
#pragma unroll
            for (int mt = 0; mt < 4; mt++) {
                uint32_t o = aaddr_nt(0, ITP * 2, wm * 64 + mt * 16, s, lane);
                ldmat4(ah[mt], sb + I_SQ0 * 2 + o);
                ldmat4(al[mt], sb + I_SQ1 * 2 + o);
            }
            {
                uint32_t bhf[2][4], blf[2][4];
#pragma unroll
                for (int p = 0; p < 2; p++) {
                    uint32_t o = baddr_nt(0, ITP * 2, wn * 32 + p * 16, s, lane);
                    ldmat4(bhf[p], sb + I_SK0 * 2 + o);
                    ldmat4(blf[p], sb + I_SK1 * 2 + o);
                }
#pragma unroll
                for (int mt = 0; mt < 4; mt++)
#pragma unroll
                    for (int j = 0; j < 4; j++) {
                        const int p = j >> 1, hs = (j & 1) * 2;
                        mma3(accS[mt][j], ah[mt], al[mt], bhf[p][hs], bhf[p][hs + 1], blf[p][hs], blf[p][hs + 1]);
                    }
            }
            {
                uint32_t bhf[2][4], blf[2][4];
#pragma unroll
                for (int p = 0; p < 2; p++) {
                    uint32_t o = baddr_t(0, ISP * 2, wn * 32 + p * 16, s, lane);
                    ldmat4t(bhf[p], sb + I_SV0 * 2 + o);
                    ldmat4t(blf[p], sb + I_SV1 * 2 + o);
                }
#pragma unroll
                for (int mt = 0; mt < 4; mt++)
#pragma unroll
                    for (int j = 0; j < 4; j++) {
                        const int p = j >> 1, hs = (j & 1) * 2;
                        mma3(accN[mt][j], ah[mt], al[mt], bhf[p][hs], bhf[p][hs + 1], blf[p][hs], blf[p][hs + 1]);
                    }
            }
        }
        __syncthreads();
    }

    // -------- mask + rowsum + split-store S --------
    if (tid < 128) dens[tid] = 0.f;
    __syncthreads();
#pragma unroll
    for (int mt = 0; mt < 4; mt++) {
        int mlo = wm * 64 + mt * 16 + gr, mhi = mlo + 8;
        float r0 = 0.f, r1 = 0.f;
#pragma unroll
        for (int j = 0; j < 4; j++) {
            int n = wn * 32 + j * 8 + gc;
            float v0 = (n     <= mlo) ? accS[mt][j][0] : 0.f;
            float v1 = (n + 1 <= mlo) ? accS[mt][j][1] : 0.f;
            float v2 = (n     <= mhi) ? accS[mt][j][2] : 0.f;
            float v3 = (n + 1 <= mhi) ? accS[mt][j][3] : 0.f;
            r0 += v0 + v1; r1 += v2 + v3;
            __nv_bfloat16 h0, l0, h1, l1;
            split2(v0, h0, l0); split2(v1, h1, l1);
            *(__nv_bfloat162*)&sm[I_SH + mlo * ISP + n] = __nv_bfloat162(h0, h1);
            *(__nv_bfloat162*)&sm[I_SL + mlo * ISP + n] = __nv_bfloat162(l0, l1);
            split2(v2, h0, l0); split2(v3, h1, l1);
            *(__nv_bfloat162*)&sm[I_SH + mhi * ISP + n] = __nv_bfloat162(h0, h1);
            *(__nv_bfloat162*)&sm[I_SL + mhi * ISP + n] = __nv_bfloat162(l0, l1);
        }
        r0 += __shfl_xor_sync(0xffffffffu, r0, 1);
        r0 += __shfl_xor_sync(0xffffffffu, r0, 2);
        r1 += __shfl_xor_sync(0xffffffffu, r1, 1);
        r1 += __shfl_xor_sync(0xffffffffu, r1, 2);
        if ((lane & 3) == 0) { atomicAdd(&dens[mlo], r0); atomicAdd(&dens[mhi], r1); }
    }
    __syncthreads();

    // -------- phase 2: acc2 = S @ v --------
    float acc2[4][4][4] = {};
    for (int ss = 0; ss < CHUNK; ss += 32) {
#pragma unroll
        for (int it = 0; it < 2; it++) {
            int idx = tid + it * 256;
            int r = idx >> 4, sg = idx & 15;
            size_t g = ((size_t)b * TSEQ + t0 + ss + r) * HID + h * DV + sg * 8;
            *(uint4*)&sm[I_SV0 + r * ISP + sg * 8] = *(const uint4*)(vh + g);
            *(uint4*)&sm[I_SV1 + r * ISP + sg * 8] = *(const uint4*)(vl + g);
        }
        __syncthreads();
#pragma unroll
        for (int s = 0; s < 32; s += 16) {
            uint32_t ah[4][4], al[4][4];
#pragma unroll
            for (int mt = 0; mt < 4; mt++) {
                uint32_t o = aaddr_nt(0, ISP * 2, wm * 64 + mt * 16, ss + s, lane);
                ldmat4(ah[mt], sb + I_SH * 2 + o);
                ldmat4(al[mt], sb + I_SL * 2 + o);
            }
            uint32_t bhf[2][4], blf[2][4];
#pragma unroll
            for (int p = 0; p < 2; p++) {
                uint32_t o = baddr_t(0, ISP * 2, wn * 32 + p * 16, s, lane);
                ldmat4t(bhf[p], sb + I_SV0 * 2 + o);
                ldmat4t(blf[p], sb + I_SV1 * 2 + o);
            }
#pragma unroll
            for (int mt = 0; mt < 4; mt++)
#pragma unroll
                for (int j = 0; j < 4; j++) {
                    const int p = j >> 1, hs = (j & 1) * 2;
                    mma3(acc2[mt][j], ah[mt], al[mt], bhf[p][hs], bhf[p][hs + 1], blf[p][hs], blf[p][hs + 1]);
                }
        }
        __syncthreads();
    }

    // -------- finalize: y = (accN + acc2)/den, write split-bf16 --------
#pragma unroll
    for (int mt = 0; mt < 4; mt++) {
        int mlo = wm * 64 + mt * 16 + gr, mhi = mlo + 8;
        int tlo = t0 + mlo, thi = t0 + mhi;
        float inv0 = 1.f / (denin[(size_t)bh * TSEQ + tlo] + dens[mlo] + EPSV);
        float inv1 = 1.f / (denin[(size_t)bh * TSEQ + thi] + dens[mhi] + EPSV);
#pragma unroll
        for (int j = 0; j < 4; j++) {
            int n = wn * 32 + j * 8 + gc;
            float y00 = (accN[mt][j][0] + acc2[mt][j][0]) * inv0;
            float y01 = (accN[mt][j][1] + acc2[mt][j][1]) * inv0;
            float y10 = (accN[mt][j][2] + acc2[mt][j][2]) * inv1;
            float y11 = (accN[mt][j][3] + acc2[mt][j][3]) * inv1;
            size_t o0 = ((size_t)b * TSEQ + tlo) * HID + h * DV + n;
            size_t o1 = ((size_t)b * TSEQ + thi) * HID + h * DV + n;
            __nv_bfloat16 h0, l0, h1, l1;
            split2(y00, h0, l0); split2(y01, h1, l1);
            *(__nv_bfloat162*)(yh + o0) = __nv_bfloat162(h0, h1);
            *(__nv_bfloat162*)(yl + o0) = __nv_bfloat162(l0, l1);
            split2(y10, h0, l0); split2(y11, h1, l1);
            *(__nv_bfloat162*)(yh + o1) = __nv_bfloat162(h0, h1);
            *(__nv_bfloat162*)(yl + o1) = __nv_bfloat162(l0, l1);
        }
    }
}

// ---------------- launch (stream-parallel DAG, capture-safe fork/join) ----------------
extern "C" void kernel_launch(void* const* d_in, const int* in_sizes, int n_in,
                              void* d_out, int out_size) {
    const float* x  = (const float*)d_in[0];
    const float* Wq = (const float*)d_in[1];
    const float* Wk = (const float*)d_in[2];
    const float* Wv = (const float*)d_in[3];
    const float* Wo = (const float*)d_in[4];
    float* out = (float*)d_out;

    float *pqk, *pkv, *pk1, *pden;
    cudaGetSymbolAddress((void**)&pqk,  g_qk);
    cudaGetSymbolAddress((void**)&pkv,  g_kv);
    cudaGetSymbolAddress((void**)&pk1,  g_k1);
    cudaGetSymbolAddress((void**)&pden, g_den);

    __nv_bfloat16 *xh, *xl, *yh, *yl, *vh, *vl, *qfh, *qfl, *kfh, *kfl, *kvh, *kvl;
    __nv_bfloat16 *wqkh, *wqkl, *wvh, *wvl, *woh, *wol;
    cudaGetSymbolAddress((void**)&xh, g_xh);   cudaGetSymbolAddress((void**)&xl, g_xl);
    cudaGetSymbolAddress((void**)&yh, g_yh);   cudaGetSymbolAddress((void**)&yl, g_yl);
    cudaGetSymbolAddress((void**)&vh, g_vh);   cudaGetSymbolAddress((void**)&vl, g_vl);
    cudaGetSymbolAddress((void**)&qfh, g_qfh); cudaGetSymbolAddress((void**)&qfl, g_qfl);
    cudaGetSymbolAddress((void**)&kfh, g_kfh); cudaGetSymbolAddress((void**)&kfl, g_kfl);
    cudaGetSymbolAddress((void**)&kvh, g_kvh); cudaGetSymbolAddress((void**)&kvl, g_kvl);
    cudaGetSymbolAddress((void**)&wqkh, g_wqkh); cudaGetSymbolAddress((void**)&wqkl, g_wqkl);
    cudaGetSymbolAddress((void**)&wvh, g_wvh); cudaGetSymbolAddress((void**)&wvl, g_wvl);
    cudaGetSymbolAddress((void**)&woh, g_woh); cudaGetSymbolAddress((void**)&wol, g_wol);

    cudaFuncSetAttribute(gemm_mma<false>, cudaFuncAttributeMaxDynamicSharedMemorySize, SMEM_MMA);
    cudaFuncSetAttribute(gemm_mma<true>,  cudaFuncAttributeMaxDynamicSharedMemorySize, SMEM_MMA);
    cudaFuncSetAttribute(intra_mma, cudaFuncAttributeMaxDynamicSharedMemorySize, SMEM_INTRA);

    static cudaStream_t s1 = nullptr, s2 = nullptr;
    static cudaEvent_t evB = nullptr, evX = nullptr, evWk = nullptr, evWv = nullptr,
                       evQ = nullptr, evK = nullptr, evDen = nullptr, evWo = nullptr;
    if (s1 == nullptr) {
        cudaStreamCreateWithFlags(&s1, cudaStreamNonBlocking);
        cudaStreamCreateWithFlags(&s2, cudaStreamNonBlocking);
        cudaEventCreateWithFlags(&evB,   cudaEventDisableTiming);
        cudaEventCreateWithFlags(&evX,   cudaEventDisableTiming);
        cudaEventCreateWithFlags(&evWk,  cudaEventDisableTiming);
        cudaEventCreateWithFlags(&evWv,  cudaEventDisableTiming);
        cudaEventCreateWithFlags(&evQ,   cudaEventDisableTiming);
        cudaEventCreateWithFlags(&evK,   cudaEventDisableTiming);
        cudaEventCreateWithFlags(&evDen, cudaEventDisableTiming);
        cudaEventCreateWithFlags(&evWo,  cudaEventDisableTiming);
    }

    // fork side streams from the (captured) default stream
    cudaEventRecord(evB, 0);
    cudaStreamWaitEvent(s1, evB, 0);
    cudaStreamWaitEvent(s2, evB, 0);

    // LAUNCH ORDER NOTE: cvt_x submitted first so the 6th submitted kernel is the
    // QK gemm (for ncu -s 5 -c 1 visibility into the GEMM next round).
    cvt_split<<<(BT * HID / 4) / 256, 256>>>(x, xh, xl, (size_t)BT * HID);          // #1
    cudaEventRecord(evX, 0);

    cvt_split<<<(QKDIM * HID / 4) / 256, 256, 0, s1>>>(Wq, wqkh, wqkl, (size_t)QKDIM * HID); // #2
    cvt_split<<<(QKDIM * HID / 4) / 256, 256, 0, s2>>>(
        Wk, wqkh + (size_t)QKDIM * HID, wqkl + (size_t)QKDIM * HID, (size_t)QKDIM * HID);    // #3
    cudaEventRecord(evWk, s2);
    cvt_split<<<(HID * HID / 4) / 256, 256, 0, s2>>>(Wv, wvh, wvl, (size_t)HID * HID);       // #4
    cudaEventRecord(evWv, s2);
    cvt_split<<<(HID * HID / 4) / 256, 256, 0, s2>>>(Wo, woh, wol, (size_t)HID * HID);       // #5
    cudaEventRecord(evWo, s2);

    // s1: fused QK projection chain                                                 // #6 = GEMM
    cudaStreamWaitEvent(s1, evX, 0);
    cudaStreamWaitEvent(s1, evWk, 0);
    gemm_mma<false><<<dim3(QK2 / 128, BT / 128), 512, SMEM_MMA, s1>>>(
        xh, xl, wqkh, wqkl, pqk, nullptr, nullptr, BT, QK2, HID);
    taylor_split<<<(BH * TSEQ) / 8, 256, 0, s1>>>(pqk, QK2, 0, qfh, qfl);
    cudaEventRecord(evQ, s1);
    taylor_split<<<(BH * TSEQ) / 8, 256, 0, s1>>>(pqk, QK2, QKDIM, kfh, kfl);
    cudaEventRecord(evK, s1);
    k1_sum_kernel<<<(NCH * DP) / 256, 256, 0, s1>>>(kfh, kfl, pk1);
    scan_k1_kernel<<<(BH * DP + 255) / 256, 256, 0, s1>>>(pk1);
    den_inter_kernel<<<(BH * TSEQ) / 8, 256, 0, s1>>>(qfh, qfl, pk1, pden);
    cudaEventRecord(evDen, s1);

    // main: V projection writing split bf16 directly (Wv cvt done on s2)
    cudaStreamWaitEvent(0, evWv, 0);
    gemm_mma<true><<<dim3(HID / 128, BT / 128), 512, SMEM_MMA>>>(
        xh, xl, wvh, wvl, nullptr, vh, vl, BT, HID, HID);

    // main: pass1 (1920 CTAs) -> fused scan+split (needs kf)
    cudaStreamWaitEvent(0, evK, 0);
    pass1_mma<<<dim3(DP / 64, NCH), 256>>>(kfh, kfl, vh, vl, pkv);
    scan_kv_kernel<<<(BH * DP * DV) / 256, 256>>>(pkv, kvh, kvl);

    // main: fused inter+intra (needs qf, den)
    cudaStreamWaitEvent(0, evQ, 0);
    cudaStreamWaitEvent(0, evDen, 0);
    intra_mma<<<NCH, 256, SMEM_INTRA>>>(qfh, qfl, kfh, kfl, kvh, kvl, vh, vl, pden, yh, yl);

    // main: output projection (needs Wo cvt)
    cudaStreamWaitEvent(0, evWo, 0);
    gemm_mma<false><<<dim3(HID / 128, BT / 128), 512, SMEM_MMA>>>(
        yh, yl, woh, wol, out, nullptr, nullptr, BT, HID, HID);
}

// round 14
// speedup vs baseline: 1.3143x; 1.0139x over previous
#include <cuda_runtime.h>
#include <cuda_bf16.h>
#include <cstdint>

// ---------------- problem constants ----------------
#define BATCH  2
#define TSEQ   2048
#define BT     4096      // BATCH*TSEQ
#define HID    1536
#define NH     12
#define DK     16
#define DV     128
#define QKDIM  192       // NH*DK
#define QK2    384       // fused Q+K projection width
#define DREAL  273       // 1 + 16 + 256
#define DP     320       // padded feature dim
#define CHUNK  128
#define NCK    16        // TSEQ/CHUNK
#define BH     24        // BATCH*NH
#define NCH    384       // BH*NCK
#define EPSV   1e-12f

// ---------------- scratch (device globals, alloc-free) ----------------
__device__ float g_qk [(size_t)BT*QK2];
__device__ float g_kv [(size_t)NCH*DP*DV];
__device__ float g_k1 [(size_t)NCH*DP];
__device__ float g_den[(size_t)BH*TSEQ];

// bf16 split operands
__device__ __nv_bfloat16 g_xh [(size_t)BT*HID];
__device__ __nv_bfloat16 g_xl [(size_t)BT*HID];
__device__ __nv_bfloat16 g_yh [(size_t)BT*HID];
__device__ __nv_bfloat16 g_yl [(size_t)BT*HID];
__device__ __nv_bfloat16 g_vh [(size_t)BT*HID];
__device__ __nv_bfloat16 g_vl [(size_t)BT*HID];
__device__ __nv_bfloat16 g_qfh[(size_t)BH*TSEQ*DP];
__device__ __nv_bfloat16 g_qfl[(size_t)BH*TSEQ*DP];
__device__ __nv_bfloat16 g_kfh[(size_t)BH*TSEQ*DP];
__device__ __nv_bfloat16 g_kfl[(size_t)BH*TSEQ*DP];
__device__ __nv_bfloat16 g_kvh[(size_t)NCH*DP*DV];
__device__ __nv_bfloat16 g_kvl[(size_t)NCH*DP*DV];
__device__ __nv_bfloat16 g_wqkh[(size_t)QK2*HID];
__device__ __nv_bfloat16 g_wqkl[(size_t)QK2*HID];
__device__ __nv_bfloat16 g_wvh[(size_t)HID*HID];
__device__ __nv_bfloat16 g_wvl[(size_t)HID*HID];
__device__ __nv_bfloat16 g_woh[(size_t)HID*HID];
__device__ __nv_bfloat16 g_wol[(size_t)HID*HID];

// ---------------- helpers ----------------
__device__ __forceinline__ uint32_t smem_u32(const void* p) {
    uint32_t a;
    asm("{ .reg .u64 t; cvta.to.shared.u64 t, %1; cvt.u32.u64 %0, t; }" : "=r"(a) : "l"(p));
    return a;
}
__device__ __forceinline__ void cp_async16(uint32_t dst, const void* src) {
    asm volatile("cp.async.cg.shared.global [%0], [%1], 16;" :: "r"(dst), "l"(src));
}
#define CP_COMMIT() asm volatile("cp.async.commit_group;" ::: "memory")
#define CP_WAIT(N)  asm volatile("cp.async.wait_group %0;" :: "n"(N) : "memory")

__device__ __forceinline__ void ldmat4(uint32_t* r, uint32_t addr) {
    asm volatile("ldmatrix.sync.aligned.m8n8.x4.shared.b16 {%0,%1,%2,%3}, [%4];"
                 : "=r"(r[0]), "=r"(r[1]), "=r"(r[2]), "=r"(r[3]) : "r"(addr));
}
__device__ __forceinline__ void ldmat4t(uint32_t* r, uint32_t addr) {
    asm volatile("ldmatrix.sync.aligned.m8n8.x4.trans.shared.b16 {%0,%1,%2,%3}, [%4];"
                 : "=r"(r[0]), "=r"(r[1]), "=r"(r[2]), "=r"(r[3]) : "r"(addr));
}
__device__ __forceinline__ void mma_bf16(float* d,
                                         uint32_t a0, uint32_t a1, uint32_t a2, uint32_t a3,
                                         uint32_t b0, uint32_t b1) {
    asm volatile("mma.sync.aligned.m16n8k16.row.col.f32.bf16.bf16.f32 "
                 "{%0,%1,%2,%3}, {%4,%5,%6,%7}, {%8,%9}, {%0,%1,%2,%3};"
                 : "+f"(d[0]), "+f"(d[1]), "+f"(d[2]), "+f"(d[3])
                 : "r"(a0), "r"(a1), "r"(a2), "r"(a3), "r"(b0), "r"(b1));
}
// split-3 product: Ah*Bh + Ah*Bl + Al*Bh
__device__ __forceinline__ void mma3(float* d, const uint32_t* ah, const uint32_t* al,
                                     uint32_t bh0, uint32_t bh1, uint32_t bl0, uint32_t bl1) {
    mma_bf16(d, ah[0], ah[1], ah[2], ah[3], bh0, bh1);
    mma_bf16(d, ah[0], ah[1], ah[2], ah[3], bl0, bl1);
    mma_bf16(d, al[0], al[1], al[2], al[3], bh0, bh1);
}

// fragment address helpers (lane-dependent); pitchB = row pitch in bytes
__device__ __forceinline__ uint32_t aaddr_nt(uint32_t base, int pitchB, int m_off, int k_off, int lane) {
    int row = m_off + (lane & 7) + ((lane >> 3) & 1) * 8;
    int col = k_off + ((lane >> 4) & 1) * 8;
    return base + row * pitchB + col * 2;
}
__device__ __forceinline__ uint32_t aaddr_t(uint32_t base, int pitchB, int m_off, int k_off, int lane) {
    int row = k_off + (lane & 7) + ((lane >> 4) & 1) * 8;
    int col = m_off + ((lane >> 3) & 1) * 8;
    return base + row * pitchB + col * 2;
}
__device__ __forceinline__ uint32_t baddr_nt(uint32_t base, int pitchB, int n_off, int k_off, int lane) {
    int row = n_off + (lane & 7) + ((lane >> 4) & 1) * 8;
    int col = k_off + ((lane >> 3) & 1) * 8;
    return base + row * pitchB + col * 2;
}
__device__ __forceinline__ uint32_t baddr_t(uint32_t base, int pitchB, int n_off, int k_off, int lane) {
    int row = k_off + (lane & 7) + ((lane >> 3) & 1) * 8;
    int col = n_off + ((lane >> 4) & 1) * 8;
    return base + row * pitchB + col * 2;
}

__device__ __forceinline__ void split2(float v, __nv_bfloat16& h, __nv_bfloat16& l) {
    h = __float2bfloat16(v);
    l = __float2bfloat16(v - __bfloat162float(h));
}

// ---------------- split conversion fp32 -> (hi, lo) bf16 ----------------
__global__ void cvt_split(const float* __restrict__ x, __nv_bfloat16* __restrict__ hi,
                          __nv_bfloat16* __restrict__ lo, size_t n) {
    size_t i = ((size_t)blockIdx.x * 256 + threadIdx.x) * 4;
    if (i >= n) return;
    float4 v = *(const float4*)(x + i);
    float a[4] = {v.x, v.y, v.z, v.w};
    __nv_bfloat16 h[4], l[4];
#pragma unroll
    for (int j = 0; j < 4; j++) split2(a[j], h[j], l[j]);
    ((__nv_bfloat162*)(hi + i))[0] = __nv_bfloat162(h[0], h[1]);
    ((__nv_bfloat162*)(hi + i))[1] = __nv_bfloat162(h[2], h[3]);
    ((__nv_bfloat162*)(lo + i))[0] = __nv_bfloat162(l[0], l[1]);
    ((__nv_bfloat162*)(lo + i))[1] = __nv_bfloat162(l[2], l[3]);
}

// ---------------- HMMA split-bf16 GEMM: C[M,N] = A[M,K] @ B[N,K]^T ----------------
// 512 threads (4x4 warps, 32x32 warp tiles), K-chunk 64, 2-stage cp.async ring.
#define GPITCH 72
#define MAT_BYTES (128 * GPITCH * 2)        // 18432
#define STAGE_BYTES (4 * MAT_BYTES)         // 73728
#define SMEM_MMA (2 * STAGE_BYTES)          // 147456

template <bool SPLIT>
__global__ void __launch_bounds__(512) gemm_mma(
    const __nv_bfloat16* __restrict__ Ahg, const __nv_bfloat16* __restrict__ Alg,
    const __nv_bfloat16* __restrict__ Bhg, const __nv_bfloat16* __restrict__ Blg,
    float* __restrict__ C, __nv_bfloat16* __restrict__ Ch, __nv_bfloat16* __restrict__ Cl,
    int M, int N, int K) {
    extern __shared__ char smem[];
    const uint32_t sb = smem_u32(smem);
    const int tid = threadIdx.x, wid = tid >> 5, lane = tid & 31;
    const int wm = wid >> 2, wn = wid & 3;           // 4x4 warps, 32x32 tiles
    const int m0 = blockIdx.y * 128, n0 = blockIdx.x * 128;
    const int nch = K / 64;

    float acc[2][4][4] = {};

    auto load_chunk = [&](int c, int s) {
        const uint32_t base = sb + (uint32_t)s * STAGE_BYTES;
        const int kk = c * 64;
#pragma unroll
        for (int it = 0; it < 8; it++) {
            int idx = tid + it * 512;
            int mat = idx >> 10;
            int r   = (idx >> 3) & 127;
            int seg = idx & 7;
            uint32_t dst = base + (uint32_t)mat * MAT_BYTES + (uint32_t)(r * (GPITCH * 2) + seg * 16);
            const __nv_bfloat16* src;
            if (mat < 2) {
                const __nv_bfloat16* A = (mat == 0) ? Ahg : Alg;
                src = A + (size_t)(m0 + r) * K + kk + seg * 8;
            } else {
                const __nv_bfloat16* B = (mat == 2) ? Bhg : Blg;
                src = B + (size_t)(n0 + r) * K + kk + seg * 8;
            }
            cp_async16(dst, src);
        }
        CP_COMMIT();
    };

    load_chunk(0, 0);

    for (int c = 0; c < nch; c++) {
        CP_WAIT(0);
        __syncthreads();
        if (c + 1 < nch) load_chunk(c + 1, (c + 1) & 1);

        const uint32_t base = sb + (uint32_t)(c & 1) * STAGE_BYTES;
        const uint32_t bAh = base, bAl = base + MAT_BYTES;
        const uint32_t bBh = base + 2 * MAT_BYTES, bBl = base + 3 * MAT_BYTES;
#pragma unroll
        for (int s = 0; s < 64; s += 16) {
            uint32_t ah[2][4], al[2][4];
#pragma unroll
            for (int mt = 0; mt < 2; mt++) {
                uint32_t o = aaddr_nt(0, GPITCH * 2, wm * 32 + mt * 16, s, lane);
                ldmat4(ah[mt], bAh + o);
                ldmat4(al[mt], bAl + o);
            }
            uint32_t bh[2][4], bl[2][4];
#pragma unroll
            for (int p = 0; p < 2; p++) {
                uint32_t o = baddr_nt(0, GPITCH * 2, wn * 32 + p * 16, s, lane);
                ldmat4(bh[p], bBh + o);
                ldmat4(bl[p], bBl + o);
            }
#pragma unroll
            for (int mt = 0; mt < 2; mt++)
#pragma unroll
                for (int j = 0; j < 4; j++) {
                    const int p = j >> 1, h = (j & 1) * 2;
                    mma3(acc[mt][j], ah[mt], al[mt], bh[p][h], bh[p][h + 1], bl[p][h], bl[p][h + 1]);
                }
        }
    }

    const int gr = lane >> 2, gc = (lane & 3) * 2;
#pragma unroll
    for (int mt = 0; mt < 2; mt++)
#pragma unroll
        for (int j = 0; j < 4; j++) {
            int m = m0 + wm * 32 + mt * 16 + gr;
            int n = n0 + wn * 32 + j * 8 + gc;
            if (n < N) {
                if (!SPLIT) {
                    *(float2*)(C + (size_t)m * N + n)       = make_float2(acc[mt][j][0], acc[mt][j][1]);
                    *(float2*)(C + (size_t)(m + 8) * N + n) = make_float2(acc[mt][j][2], acc[mt][j][3]);
                } else {
                    __nv_bfloat16 h0, l0, h1, l1;
                    split2(acc[mt][j][0], h0, l0); split2(acc[mt][j][1], h1, l1);
                    *(__nv_bfloat162*)(Ch + (size_t)m * N + n) = __nv_bfloat162(h0, h1);
                    *(__nv_bfloat162*)(Cl + (size_t)m * N + n) = __nv_bfloat162(l0, l1);
                    split2(acc[mt][j][2], h0, l0); split2(acc[mt][j][3], h1, l1);
                    *(__nv_bfloat162*)(Ch + (size_t)(m + 8) * N + n) = __nv_bfloat162(h0, h1);
                    *(__nv_bfloat162*)(Cl + (size_t)(m + 8) * N + n) = __nv_bfloat162(l0, l1);
                }
            }
        }
}

// ---------------- Taylor features -> split bf16 [BH, T, DP] ----------------
__global__ void taylor_split(const float* __restrict__ src, int stride, int coloff,
                             __nv_bfloat16* __restrict__ dh, __nv_bfloat16* __restrict__ dl) {
    const int row = blockIdx.x * 8 + (threadIdx.x >> 5);   // [0, BH*TSEQ)
    const int lane = threadIdx.x & 31;
    const int bh = row / TSEQ, t = row % TSEQ;
    const int b = bh / NH, h = bh % NH;
    float qv = 0.f;
    if (lane < DK) qv = src[((size_t)b * TSEQ + t) * stride + coloff + h * DK + lane];
    __nv_bfloat16* oh = dh + (size_t)row * DP;
    __nv_bfloat16* ol = dl + (size_t)row * DP;
#pragma unroll
    for (int d0 = 0; d0 < DP; d0 += 32) {
        const int d = d0 + lane;
        int i_idx, j_idx;
        if (d >= 17) { int ij = d - 17; i_idx = (ij >> 4) & 15; j_idx = ij & 15; }
        else         { i_idx = (d - 1) & 15; j_idx = 0; }
        float qi = __shfl_sync(0xffffffffu, qv, i_idx);
        float qj = __shfl_sync(0xffffffffu, qv, j_idx);
        float val;
        if (d == 0) val = 1.f;
        else if (d < 1 + DK) val = qi * 0.5f;
        else if (d < DREAL) val = qi * qj * 0.17677669529663688f;
        else val = 0.f;
        __nv_bfloat16 hh, ll; split2(val, hh, ll);
        oh[d] = hh; ol[d] = ll;
    }
}

// ---------------- pass1 (HMMA): KV[dp, dv] = kf^T @ v per chunk ----------------
#define P1KP 72
#define P1VP 136
__global__ void __launch_bounds__(256) pass1_mma(
    const __nv_bfloat16* __restrict__ kfh, const __nv_bfloat16* __restrict__ kfl,
    const __nv_bfloat16* __restrict__ vh,  const __nv_bfloat16* __restrict__ vl,
    float* __restrict__ kv) {
    __shared__ __nv_bfloat16 sk[2][32 * P1KP];
    __shared__ __nv_bfloat16 sv[2][32 * P1VP];
    const int chunk = blockIdx.y, m0 = blockIdx.x * 64;
    const int bh = chunk / NCK, c = chunk % NCK;
    const int b = bh / NH, h = bh % NH;
    const int t0 = c * CHUNK;
    const int tid = threadIdx.x, wid = tid >> 5, lane = tid & 31;
    const int wm = wid >> 2, wn = wid & 3;     // warp tile 32m x 32n
    float acc[2][4][4] = {};

    const uint32_t kb0 = smem_u32(sk[0]), kb1 = smem_u32(sk[1]);
    const uint32_t vb0 = smem_u32(sv[0]), vb1 = smem_u32(sv[1]);

    for (int tt = 0; tt < CHUNK; tt += 32) {
        {
            int r = tid >> 3, sg = tid & 7;
            size_t g = ((size_t)bh * TSEQ + t0 + tt + r) * DP + m0 + sg * 8;
            *(uint4*)&sk[0][r * P1KP + sg * 8] = *(const uint4*)(kfh + g);
            *(uint4*)&sk[1][r * P1KP + sg * 8] = *(const uint4*)(kfl + g);
        }
#pragma unroll
        for (int it = 0; it < 2; it++) {
            int idx = tid + it * 256;
            int r = idx >> 4, sg = idx & 15;
            size_t g = ((size_t)b * TSEQ + t0 + tt + r) * HID + h * DV + sg * 8;
            *(uint4*)&sv[0][r * P1VP + sg * 8] = *(const uint4*)(vh + g);
            *(uint4*)&sv[1][r * P1VP + sg * 8] = *(const uint4*)(vl + g);
        }
        __syncthreads();
#pragma unroll
        for (int s = 0; s < 32; s += 16) {
            uint32_t ah[2][4], al[2][4];
#pragma unroll
            for (int mt = 0; mt < 2; mt++) {
                uint32_t o = aaddr_t(0, P1KP * 2, wm * 32 + mt * 16, s, lane);
                ldmat4t(ah[mt], kb0 + o);
                ldmat4t(al[mt], kb1 + o);
            }
            uint32_t bhf[2][4], blf[2][4];
#pragma unroll
            for (int p = 0; p < 2; p++) {
                uint32_t o = baddr_t(0, P1VP * 2, wn * 32 + p * 16, s, lane);
                ldmat4t(bhf[p], vb0 + o);
                ldmat4t(blf[p], vb1 + o);
            }
#pragma unroll
            for (int mt = 0; mt < 2; mt++)
#pragma unroll
                for (int j = 0; j < 4; j++) {
                    const int p = j >> 1, hs = (j & 1) * 2;
                    mma3(acc[mt][j], ah[mt], al[mt], bhf[p][hs], bhf[p][hs + 1], blf[p][hs], blf[p][hs + 1]);
                }
        }
        __syncthreads();
    }
    const int gr = lane >> 2, gc = (lane & 3) * 2;
#pragma unroll
    for (int mt = 0; mt < 2; mt++)
#pragma unroll
        for (int j = 0; j < 4; j++) {
            int m = m0 + wm * 32 + mt * 16 + gr;
            int n = wn * 32 + j * 8 + gc;
            float* op = kv + ((size_t)chunk * DP + m) * DV + n;
            *(float2*)op             = make_float2(acc[mt][j][0], acc[mt][j][1]);
            *(float2*)(op + 8 * DV)  = make_float2(acc[mt][j][2], acc[mt][j][3]);
        }
}

// ---------------- per-chunk K1 = colsum(kf) ----------------
__global__ void k1_sum_kernel(const __nv_bfloat16* __restrict__ kfh,
                              const __nv_bfloat16* __restrict__ kfl,
                              float* __restrict__ k1) {
    int idx = blockIdx.x * 256 + threadIdx.x;
    if (idx >= NCH * DP) return;
    int chunk = idx / DP, d = idx % DP;
    int bh = chunk / NCK, c = chunk % NCK;
    size_t base = ((size_t)bh * TSEQ + c * CHUNK) * DP + d;
    float s = 0.f;
    for (int r = 0; r < CHUNK; r++) {
        size_t p = base + (size_t)r * DP;
        s += __bfloat162float(kfh[p]) + __bfloat162float(kfl[p]);
    }
    k1[idx] = s;
}

// ---------------- exclusive prefix scans over chunks ----------------
__global__ void scan_kv_kernel(const float* __restrict__ kv,
                               __nv_bfloat16* __restrict__ kvh,
                               __nv_bfloat16* __restrict__ kvl) {
    int idx = blockIdx.x * 256 + threadIdx.x;
    if (idx >= BH * DP * DV) return;
    int bh = idx / (DP * DV), de = idx % (DP * DV);
    float s = 0.f;
    for (int c = 0; c < NCK; c++) {
        size_t p = ((size_t)(bh * NCK + c)) * DP * DV + de;
        __nv_bfloat16 hh, ll; split2(s, hh, ll);
        kvh[p] = hh; kvl[p] = ll;
        s += kv[p];
    }
}
__global__ void scan_k1_kernel(float* __restrict__ k1) {
    int idx = blockIdx.x * 256 + threadIdx.x;
    if (idx >= BH * DP) return;
    int bh = idx / DP, d = idx % DP;
    float s = 0.f;
    for (int c = 0; c < NCK; c++) {
        size_t p = ((size_t)(bh * NCK + c)) * DP + d;
        float val = k1[p]; k1[p] = s; s += val;
    }
}

// ---------------- den inter: qf . Z1_exclusive ----------------
__global__ void den_inter_kernel(const __nv_bfloat16* __restrict__ qfh,
                                 const __nv_bfloat16* __restrict__ qfl,
                                 const float* __restrict__ k1,
                                 float* __restrict__ den) {
    int row = blockIdx.x * 8 + (threadIdx.x >> 5);
    int lane = threadIdx.x & 31;
    int bh = row / TSEQ, t = row % TSEQ;
    int chunk = bh * NCK + t / CHUNK;
    size_t qb = ((size_t)bh * TSEQ + t) * DP;
    const float* z = k1 + (size_t)chunk * DP;
    float s = 0.f;
    for (int d = lane; d < DP; d += 32)
        s += (__bfloat162float(qfh[qb + d]) + __bfloat162float(qfl[qb + d])) * z[d];
#pragma unroll
    for (int o = 16; o; o >>= 1) s += __shfl_xor_sync(0xffffffffu, s, o);
    if (lane == 0) den[row] = s;
}

// ---- fused inter+intra (HMMA, 512 threads): num = qf@Z (regs) ; S = tril(qf kf^T);
//      y_split = (num + S v)/den --------------------------------------------
#define ITP 40
#define ISP 136
#define I_SQ0 0
#define I_SQ1 (I_SQ0 + 128*ITP)
#define I_SK0 (I_SQ1 + 128*ITP)
#define I_SK1 (I_SK0 + 128*ITP)
#define I_SH  (I_SK1 + 128*ITP)
#define I_SL  (I_SH + 128*ISP)
#define I_SV0 (I_SL + 128*ISP)
#define I_SV1 (I_SV0 + 32*ISP)
#define I_END (I_SV1 + 32*ISP)
#define SMEM_INTRA (I_END * 2 + 512)

__global__ void __launch_bounds__(512) intra_mma(
    const __nv_bfloat16* __restrict__ qfh, const __nv_bfloat16* __restrict__ qfl,
    const __nv_bfloat16* __restrict__ kfh, const __nv_bfloat16* __restrict__ kfl,
    const __nv_bfloat16* __restrict__ zh,  const __nv_bfloat16* __restrict__ zl,
    const __nv_bfloat16* __restrict__ vh,  const __nv_bfloat16* __restrict__ vl,
    const float* __restrict__ denin,
    __nv_bfloat16* __restrict__ yh, __nv_bfloat16* __restrict__ yl) {
    extern __shared__ char dsm[];
    __nv_bfloat16* sm = (__nv_bfloat16*)dsm;
    float* dens = (float*)(dsm + I_END * 2);
    const uint32_t sb = smem_u32(sm);
    const int chunk = blockIdx.x;
    const int bh = chunk / NCK, c = chunk % NCK;
    const int b = bh / NH, h = bh % NH;
    const int t0 = c * CHUNK;
    const int tid = threadIdx.x, wid = tid >> 5, lane = tid & 31;
    const int wm = wid >> 2, wn = wid & 3;     // 4x4 warps, 32x32 warp tiles
    const int gr = lane >> 2, gc = (lane & 3) * 2;

    // -------- phase 1: accS = qf @ kf^T  AND  accN = qf @ Z (shared a-frags) ----
    float accS[2][4][4] = {};
    float accN[2][4][4] = {};
    for (int kk = 0; kk < DP; kk += 32) {
        {
            int r = tid >> 2, sg = tid & 3;        // 512 = 128 rows x 4 segs
            size_t gq = ((size_t)bh * TSEQ + t0 + r) * DP + kk + sg * 8;
            *(uint4*)&sm[I_SQ0 + r * ITP + sg * 8] = *(const uint4*)(qfh + gq);
            *(uint4*)&sm[I_SQ1 + r * ITP + sg * 8] = *(const uint4*)(qfl + gq);
            *(uint4*)&sm[I_SK0 + r * ITP + sg * 8] = *(const uint4*)(kfh + gq);
            *(uint4*)&sm[I_SK1 + r * ITP + sg * 8] = *(const uint4*)(kfl + gq);
        }
        {
            int r = tid >> 4, sg = tid & 15;       // 512 = 32 rows x 16 segs
            size_t g = ((size_t)chunk * DP + kk + r) * DV + sg * 8;
            *(uint4*)&sm[I_SV0 + r * ISP + sg * 8] = *(const uint4*)(zh + g);
            *(uint4*)&sm[I_SV1 + r * ISP + sg * 8] = *(const uint4*)(zl + g);
        }
        __syncthreads();
#pragma unroll
        for (int s = 0; s < 32; s += 16) {
            uint32_t ah[2][4], al[2][4];
#pragma unroll
            for (int mt = 0; mt < 2; mt++) {
                uint32_t o = aaddr_nt(0, ITP * 2, wm * 32 + mt * 16, s, lane);
                ldmat4(ah[mt], sb + I_SQ0 * 2 + o);
                ldmat4(al[mt], sb + I_SQ1 * 2 + o);
            }
            {
                uint32_t bhf[2][4], blf[2][4];
#pragma unroll
                for (int p = 0; p < 2; p++) {
                    uint32_t o = baddr_nt(0, ITP * 2, wn * 32 + p * 16, s, lane);
                    ldmat4(bhf[p], sb + I_SK0 * 2 + o);
                    ldmat4(blf[p], sb + I_SK1 * 2 + o);
                }
#pragma unroll
                for (int mt = 0; mt < 2; mt++)
#pragma unroll
                    for (int j = 0; j < 4; j++) {
                        const int p = j >> 1, hs = (j & 1) * 2;
                        mma3(accS[mt][j], ah[mt], al[mt], bhf[p][hs], bhf[p][hs + 1], blf[p][hs], blf[p][hs + 1]);
                    }
            }
            {
                uint32_t bhf[2][4], blf[2][4];
#pragma unroll
                for (int p = 0; p < 2; p++) {
                    uint32_t o = baddr_t(0, ISP * 2, wn * 32 + p * 16, s, lane);
                    ldmat4t(bhf[p], sb + I_SV0 * 2 + o);
                    ldmat4t(blf[p], sb + I_SV1 * 2 + o);
                }
#pragma unroll
                for (int mt = 0; mt < 2; mt++)
#pragma unroll
                    for (int j = 0; j < 4; j++) {
                        const int p = j >> 1, hs = (j & 1) * 2;
                        mma3(accN[mt][j], ah[mt], al[mt], bhf[p][hs], bhf[p][hs + 1], blf[p][hs], blf[p][hs + 1]);
                    }
            }
        }
        __syncthreads();
    }

    // -------- mask + rowsum + split-store S --------
    if (tid < 128) dens[tid] = 0.f;
    __syncthreads();
#pragma unroll
    for (int mt = 0; mt < 2; mt++) {
        int mlo = wm * 32 + mt * 16 + gr, mhi = mlo + 8;
        float r0 = 0.f, r1 = 0.f;
#pragma unroll
        for (int j = 0; j < 4; j++) {
            int n = wn * 32 + j * 8 + gc;
            float v0 = (n     <= mlo) ? accS[mt][j][0] : 0.f;
            float v1 = (n + 1 <= mlo) ? accS[mt][j][1] : 0.f;
            float v2 = (n     <= mhi) ? accS[mt][j][2] : 0.f;
            float v3 = (n + 1 <= mhi) ? accS[mt][j][3] : 0.f;
            r0 += v0 + v1; r1 += v2 + v3;
            __nv_bfloat16 h0, l0, h1, l1;
            split2(v0, h0, l0); split2(v1, h1, l1);
            *(__nv_bfloat162*)&sm[I_SH + mlo * ISP + n] = __nv_bfloat162(h0, h1);
            *(__nv_bfloat162*)&sm[I_SL + mlo * ISP + n] = __nv_bfloat162(l0, l1);
            split2(v2, h0, l0); split2(v3, h1, l1);
            *(__nv_bfloat162*)&sm[I_SH + mhi * ISP + n] = __nv_bfloat162(h0, h1);
            *(__nv_bfloat162*)&sm[I_SL + mhi * ISP + n] = __nv_bfloat162(l0, l1);
        }
        r0 += __shfl_xor_sync(0xffffffffu, r0, 1);
        r0 += __shfl_xor_sync(0xffffffffu, r0, 2);
        r1 += __shfl_xor_sync(0xffffffffu, r1, 1);
        r1 += __shfl_xor_sync(0xffffffffu, r1, 2);
        if ((lane & 3) == 0) { atomicAdd(&dens[mlo], r0); atomicAdd(&dens[mhi], r1); }
    }
    __syncthreads();

    // -------- phase 2: acc2 = S @ v --------
    float acc2[2][4][4] = {};
    for (int ss = 0; ss < CHUNK; ss += 32) {
        {
            int r = tid >> 4, sg = tid & 15;       // 512 = 32 rows x 16 segs
            size_t g = ((size_t)b * TSEQ + t0 + ss + r) * HID + h * DV + sg * 8;
            *(uint4*)&sm[I_SV0 + r * ISP + sg * 8] = *(const uint4*)(vh + g);
            *(uint4*)&sm[I_SV1 + r * ISP + sg * 8] = *(const uint4*)(vl + g);
        }
        __syncthreads();
#pragma unroll
        for (int s = 0; s < 32; s += 16) {
            uint32_t ah[2][4], al[2][4];
#pragma unroll
            for (int mt = 0; mt < 2; mt++) {
                uint32_t o = aaddr_nt(0, ISP * 2, wm * 32 + mt * 16, ss + s, lane);
                ldmat4(ah[mt], sb + I_SH * 2 + o);
                ldmat4(al[mt], sb + I_SL * 2 + o);
            }
            uint32_t bhf[2][4], blf[2][4];
#pragma unroll
            for (int p = 0; p < 2; p++) {
                uint32_t o = baddr_t(0, ISP * 2, wn * 32 + p * 16, s, lane);
                ldmat4t(bhf[p], sb + I_SV0 * 2 + o);
                ldmat4t(blf[p], sb + I_SV1 * 2 + o);
            }
#pragma unroll
            for (int mt = 0; mt < 2; mt++)
#pragma unroll
                for (int j = 0; j < 4; j++) {
                    const int p = j >> 1, hs = (j & 1) * 2;
                    mma3(acc2[mt][j], ah[mt], al[mt], bhf[p][hs], bhf[p][hs + 1], blf[p][hs], blf[p][hs + 1]);
                }
        }
        __syncthreads();
    }

    // -------- finalize: y = (accN + acc2)/den, write split-bf16 --------
#pragma unroll
    for (int mt = 0; mt < 2; mt++) {
        int mlo = wm * 32 + mt * 16 + gr, mhi = mlo + 8;
        int tlo = t0 + mlo, thi = t0 + mhi;
        float inv0 = 1.f / (denin[(size_t)bh * TSEQ + tlo] + dens[mlo] + EPSV);
        float inv1 = 1.f / (denin[(size_t)bh * TSEQ + thi] + dens[mhi] + EPSV);
#pragma unroll
        for (int j = 0; j < 4; j++) {
            int n = wn * 32 + j * 8 + gc;
            float y00 = (accN[mt][j][0] + acc2[mt][j][0]) * inv0;
            float y01 = (accN[mt][j][1] + acc2[mt][j][1]) * inv0;
            float y10 = (accN[mt][j][2] + acc2[mt][j][2]) * inv1;
            float y11 = (accN[mt][j][3] + acc2[mt][j][3]) * inv1;
            size_t o0 = ((size_t)b * TSEQ + tlo) * HID + h * DV + n;
            size_t o1 = ((size_t)b * TSEQ + thi) * HID + h * DV + n;
            __nv_bfloat16 h0, l0, h1, l1;
            split2(y00, h0, l0); split2(y01, h1, l1);
            *(__nv_bfloat162*)(yh + o0) = __nv_bfloat162(h0, h1);
            *(__nv_bfloat162*)(yl + o0) = __nv_bfloat162(l0, l1);
            split2(y10, h0, l0); split2(y11, h1, l1);
            *(__nv_bfloat162*)(yh + o1) = __nv_bfloat162(h0, h1);
            *(__nv_bfloat162*)(yl + o1) = __nv_bfloat162(l0, l1);
        }
    }
}

// ---------------- launch (stream-parallel DAG, capture-safe fork/join) ----------------
extern "C" void kernel_launch(void* const* d_in, const int* in_sizes, int n_in,
                              void* d_out, int out_size) {
    const float* x  = (const float*)d_in[0];
    const float* Wq = (const float*)d_in[1];
    const float* Wk = (const float*)d_in[2];
    const float* Wv = (const float*)d_in[3];
    const float* Wo = (const float*)d_in[4];
    float* out = (float*)d_out;

    float *pqk, *pkv, *pk1, *pden;
    cudaGetSymbolAddress((void**)&pqk,  g_qk);
    cudaGetSymbolAddress((void**)&pkv,  g_kv);
    cudaGetSymbolAddress((void**)&pk1,  g_k1);
    cudaGetSymbolAddress((void**)&pden, g_den);

    __nv_bfloat16 *xh, *xl, *yh, *yl, *vh, *vl, *qfh, *qfl, *kfh, *kfl, *kvh, *kvl;
    __nv_bfloat16 *wqkh, *wqkl, *wvh, *wvl, *woh, *wol;
    cudaGetSymbolAddress((void**)&xh, g_xh);   cudaGetSymbolAddress((void**)&xl, g_xl);
    cudaGetSymbolAddress((void**)&yh, g_yh);   cudaGetSymbolAddress((void**)&yl, g_yl);
    cudaGetSymbolAddress((void**)&vh, g_vh);   cudaGetSymbolAddress((void**)&vl, g_vl);
    cudaGetSymbolAddress((void**)&qfh, g_qfh); cudaGetSymbolAddress((void**)&qfl, g_qfl);
    cudaGetSymbolAddress((void**)&kfh, g_kfh); cudaGetSymbolAddress((void**)&kfl, g_kfl);
    cudaGetSymbolAddress((void**)&kvh, g_kvh); cudaGetSymbolAddress((void**)&kvl, g_kvl);
    cudaGetSymbolAddress((void**)&wqkh, g_wqkh); cudaGetSymbolAddress((void**)&wqkl, g_wqkl);
    cudaGetSymbolAddress((void**)&wvh, g_wvh); cudaGetSymbolAddress((void**)&wvl, g_wvl);
    cudaGetSymbolAddress((void**)&woh, g_woh); cudaGetSymbolAddress((void**)&wol, g_wol);

    cudaFuncSetAttribute(gemm_mma<false>, cudaFuncAttributeMaxDynamicSharedMemorySize, SMEM_MMA);
    cudaFuncSetAttribute(gemm_mma<true>,  cudaFuncAttributeMaxDynamicSharedMemorySize, SMEM_MMA);
    cudaFuncSetAttribute(intra_mma, cudaFuncAttributeMaxDynamicSharedMemorySize, SMEM_INTRA);

    static cudaStream_t s1 = nullptr, s2 = nullptr;
    static cudaEvent_t evB = nullptr, evX = nullptr, evWk = nullptr, evWv = nullptr,
                       evQ = nullptr, evK = nullptr, evDen = nullptr, evWo = nullptr;
    if (s1 == nullptr) {
        cudaStreamCreateWithFlags(&s1, cudaStreamNonBlocking);
        cudaStreamCreateWithFlags(&s2, cudaStreamNonBlocking);
        cudaEventCreateWithFlags(&evB,   cudaEventDisableTiming);
        cudaEventCreateWithFlags(&evX,   cudaEventDisableTiming);
        cudaEventCreateWithFlags(&evWk,  cudaEventDisableTiming);
        cudaEventCreateWithFlags(&evWv,  cudaEventDisableTiming);
        cudaEventCreateWithFlags(&evQ,   cudaEventDisableTiming);
        cudaEventCreateWithFlags(&evK,   cudaEventDisableTiming);
        cudaEventCreateWithFlags(&evDen, cudaEventDisableTiming);
        cudaEventCreateWithFlags(&evWo,  cudaEventDisableTiming);
    }

    // fork side streams from the (captured) default stream
    cudaEventRecord(evB, 0);
    cudaStreamWaitEvent(s1, evB, 0);
    cudaStreamWaitEvent(s2, evB, 0);

    cvt_split<<<(BT * HID / 4) / 256, 256>>>(x, xh, xl, (size_t)BT * HID);
    cudaEventRecord(evX, 0);

    cvt_split<<<(QKDIM * HID / 4) / 256, 256, 0, s1>>>(Wq, wqkh, wqkl, (size_t)QKDIM * HID);
    cvt_split<<<(QKDIM * HID / 4) / 256, 256, 0, s2>>>(
        Wk, wqkh + (size_t)QKDIM * HID, wqkl + (size_t)QKDIM * HID, (size_t)QKDIM * HID);
    cudaEventRecord(evWk, s2);
    cvt_split<<<(HID * HID / 4) / 256, 256, 0, s2>>>(Wv, wvh, wvl, (size_t)HID * HID);
    cudaEventRecord(evWv, s2);
    cvt_split<<<(HID * HID / 4) / 256, 256, 0, s2>>>(Wo, woh, wol, (size_t)HID * HID);
    cudaEventRecord(evWo, s2);

    // s1: fused QK projection chain
    cudaStreamWaitEvent(s1, evX, 0);
    cudaStreamWaitEvent(s1, evWk, 0);
    gemm_mma<false><<<dim3(QK2 / 128, BT / 128), 512, SMEM_MMA, s1>>>(
        xh, xl, wqkh, wqkl, pqk, nullptr, nullptr, BT, QK2, HID);
    taylor_split<<<(BH * TSEQ) / 8, 256, 0, s1>>>(pqk, QK2, 0, qfh, qfl);
    cudaEventRecord(evQ, s1);
    taylor_split<<<(BH * TSEQ) / 8, 256, 0, s1>>>(pqk, QK2, QKDIM, kfh, kfl);
    cudaEventRecord(evK, s1);
    k1_sum_kernel<<<(NCH * DP) / 256, 256, 0, s1>>>(kfh, kfl, pk1);
    scan_k1_kernel<<<(BH * DP + 255) / 256, 256, 0, s1>>>(pk1);
    den_inter_kernel<<<(BH * TSEQ) / 8, 256, 0, s1>>>(qfh, qfl, pk1, pden);
    cudaEventRecord(evDen, s1);

    // main: V projection writing split bf16 directly (Wv cvt done on s2)
    cudaStreamWaitEvent(0, evWv, 0);
    gemm_mma<true><<<dim3(HID / 128, BT / 128), 512, SMEM_MMA>>>(
        xh, xl, wvh, wvl, nullptr, vh, vl, BT, HID, HID);

    // main: pass1 (1920 CTAs) -> fused scan+split (needs kf)
    cudaStreamWaitEvent(0, evK, 0);
    pass1_mma<<<dim3(DP / 64, NCH), 256>>>(kfh, kfl, vh, vl, pkv);
    scan_kv_kernel<<<(BH * DP * DV) / 256, 256>>>(pkv, kvh, kvl);

    // main: fused inter+intra (needs qf, den) — now 512 threads
    cudaStreamWaitEvent(0, evQ, 0);
    cudaStreamWaitEvent(0, evDen, 0);
    intra_mma<<<NCH, 512, SMEM_INTRA>>>(qfh, qfl, kfh, kfl, kvh, kvl, vh, vl, pden, yh, yl);

    // main: output projection (needs Wo cvt)
    cudaStreamWaitEvent(0, evWo, 0);
    gemm_mma<false><<<dim3(HID / 128, BT / 128), 512, SMEM_MMA>>>(
        yh, yl, woh, wol, out, nullptr, nullptr, BT, HID, HID);
}